// round 1
// baseline (speedup 1.0000x reference)
#include <cuda_runtime.h>
#include <math.h>

#define BATCH 2
#define SEQ   2048
#define HID   2048
#define NH    16
#define HD    128
#define MTOT  (BATCH*SEQ)

#define BQ    64
#define BKV   64
#define QKS   68      // padded stride for d-major Q/K smem tiles
#define PS    65      // padded stride for P tile
#define ATTN_SMEM_FLOATS (128*QKS*2 + BKV*HD + BQ*PS)
#define ATTN_SMEM_BYTES  (ATTN_SMEM_FLOATS*4)

// ---------------- device scratch (no allocation allowed) ----------------
__device__ float g_Q[(size_t)MTOT*HID];   // Q projection   (B,S,H*D)
__device__ float g_K[(size_t)MTOT*HD];    // K projection   (B,S,D)
__device__ float g_V[(size_t)MTOT*HD];    // V projection   (B,S,D)
__device__ float g_A[(size_t)MTOT*HID];   // attention out  (B,S,H*D)
__device__ int   g_allones;

// ---------------- mask pre-scan ----------------
__global__ void flag_init_kernel() { g_allones = 1; }

__global__ void mask_scan_kernel(const int* __restrict__ mask) {
    const int4* m4 = (const int4*)mask;
    const int total = BATCH*SEQ*SEQ/4;
    int bad = 0;
    for (int i = blockIdx.x*blockDim.x + threadIdx.x; i < total;
         i += gridDim.x*blockDim.x) {
        int4 v = m4[i];
        if ((v.x == 0) | (v.y == 0) | (v.z == 0) | (v.w == 0)) bad = 1;
    }
    if (bad) g_allones = 0;
}

// ---------------- generic SGEMM + bias: C[M,N] = A[M,K]@B[K,N] + bias ----------------
// 128x128 block tile, BK=8, 256 threads, 8x8 per-thread micro-tile.
__global__ __launch_bounds__(256) void sgemm_bias_kernel(
    const float* __restrict__ A, const float* __restrict__ B,
    const float* __restrict__ bias, float* __restrict__ C,
    int M, int N, int K)
{
    __shared__ float As[8][128];
    __shared__ float Bs[8][128];
    const int tid  = threadIdx.x;
    const int tx   = tid & 15;         // 0..15  (col group)
    const int ty   = tid >> 4;         // 0..15  (row group)
    const int row0 = blockIdx.y * 128;
    const int col0 = blockIdx.x * 128;

    const int arow = tid >> 1;         // 0..127
    const int acol = (tid & 1) * 4;    // 0 or 4
    const int brow = tid >> 5;         // 0..7
    const int bcol = (tid & 31) * 4;   // 0..124

    float acc[8][8];
#pragma unroll
    for (int i = 0; i < 8; i++)
#pragma unroll
        for (int j = 0; j < 8; j++) acc[i][j] = 0.f;

    const float* Aptr = A + (size_t)(row0 + arow) * K + acol;
    const float* Bptr = B + (size_t)brow * N + col0 + bcol;

    for (int k0 = 0; k0 < K; k0 += 8) {
        float4 av = *(const float4*)(Aptr + k0);
        float4 bv = *(const float4*)(Bptr + (size_t)k0 * N);
        As[acol+0][arow] = av.x;
        As[acol+1][arow] = av.y;
        As[acol+2][arow] = av.z;
        As[acol+3][arow] = av.w;
        *(float4*)&Bs[brow][bcol] = bv;
        __syncthreads();
#pragma unroll
        for (int kk = 0; kk < 8; kk++) {
            float ar[8], br[8];
            *(float4*)&ar[0] = *(const float4*)&As[kk][ty*8];
            *(float4*)&ar[4] = *(const float4*)&As[kk][ty*8+4];
            *(float4*)&br[0] = *(const float4*)&Bs[kk][tx*8];
            *(float4*)&br[4] = *(const float4*)&Bs[kk][tx*8+4];
#pragma unroll
            for (int i = 0; i < 8; i++)
#pragma unroll
                for (int j = 0; j < 8; j++)
                    acc[i][j] += ar[i] * br[j];
        }
        __syncthreads();
    }

#pragma unroll
    for (int i = 0; i < 8; i++) {
        const int r = row0 + ty*8 + i;
        float* crow = C + (size_t)r * N + col0 + tx*8;
        const float* bp = bias + col0 + tx*8;
        float4 o0, o1;
        o0.x = acc[i][0] + bp[0];
        o0.y = acc[i][1] + bp[1];
        o0.z = acc[i][2] + bp[2];
        o0.w = acc[i][3] + bp[3];
        o1.x = acc[i][4] + bp[4];
        o1.y = acc[i][5] + bp[5];
        o1.z = acc[i][6] + bp[6];
        o1.w = acc[i][7] + bp[7];
        *(float4*)crow     = o0;
        *(float4*)(crow+4) = o1;
    }
}

// ---------------- flash attention (fp32, online softmax) ----------------
// grid (SEQ/BQ, NH, BATCH); 128 threads.
// Thread (ty=tid/8, tx=tid%8): score tile rows ty*4+i (i<4), cols tx*8+j (j<8);
// O tile rows ty*4+i, cols tx*16+c (c<16).
__global__ __launch_bounds__(128) void attn_kernel(const int* __restrict__ mask)
{
    extern __shared__ float sm[];
    float* sQt = sm;                    // [128][QKS] d-major: sQt[d*QKS + r]
    float* sKt = sQt + 128*QKS;         // [128][QKS] d-major: sKt[d*QKS + kc]
    float* sV  = sKt + 128*QKS;         // [BKV][HD]  row-major
    float* sP  = sV  + BKV*HD;          // [BQ][PS]   row-major padded

    const int qb  = blockIdx.x;
    const int h   = blockIdx.y;
    const int b   = blockIdx.z;
    const int tid = threadIdx.x;
    const int tx  = tid & 7;
    const int ty  = tid >> 3;
    const int q0  = qb * BQ;
    const int allones = g_allones;

    // Load Q tile, transposing to d-major. Lane-varying r keeps smem writes
    // conflict-free; global reads are 16B/lane from distinct rows (sector-OK).
    for (int e = tid; e < BQ*32; e += 128) {
        int r  = e & 63;
        int c4 = e >> 6;
        float4 v = *(const float4*)&g_Q[((size_t)(b*SEQ + q0 + r))*HID + h*HD + c4*4];
        int d = c4*4;
        sQt[(d+0)*QKS + r] = v.x;
        sQt[(d+1)*QKS + r] = v.y;
        sQt[(d+2)*QKS + r] = v.z;
        sQt[(d+3)*QKS + r] = v.w;
    }

    float m_i[4], l_i[4], acc[4][16];
#pragma unroll
    for (int i = 0; i < 4; i++) {
        m_i[i] = -1e30f;
        l_i[i] = 0.f;
#pragma unroll
        for (int c = 0; c < 16; c++) acc[i][c] = 0.f;
    }

    for (int j0 = 0; j0 < SEQ; j0 += BKV) {
        __syncthreads();   // previous PV done before K/V/P tiles are reused
        // K tile -> d-major
        for (int e = tid; e < BKV*32; e += 128) {
            int r  = e & 63;
            int c4 = e >> 6;
            float4 v = *(const float4*)&g_K[((size_t)(b*SEQ + j0 + r))*HD + c4*4];
            int d = c4*4;
            sKt[(d+0)*QKS + r] = v.x;
            sKt[(d+1)*QKS + r] = v.y;
            sKt[(d+2)*QKS + r] = v.z;
            sKt[(d+3)*QKS + r] = v.w;
        }
        // V tile -> row-major (rows are contiguous in g_V: straight copy)
        for (int e = tid; e < BKV*32; e += 128) {
            ((float4*)sV)[e] = *(const float4*)&g_V[((size_t)(b*SEQ + j0))*HD + e*4];
        }
        __syncthreads();

        // ---- scores: S = Q @ K^T ----
        float s[4][8];
#pragma unroll
        for (int i = 0; i < 4; i++)
#pragma unroll
            for (int j = 0; j < 8; j++) s[i][j] = 0.f;

#pragma unroll 4
        for (int d = 0; d < HD; d++) {
            float4 qv = *(const float4*)&sQt[d*QKS + ty*4];
            float4 k0 = *(const float4*)&sKt[d*QKS + tx*8];
            float4 k1 = *(const float4*)&sKt[d*QKS + tx*8 + 4];
            float q[4]  = {qv.x, qv.y, qv.z, qv.w};
            float kv[8] = {k0.x,k0.y,k0.z,k0.w,k1.x,k1.y,k1.z,k1.w};
#pragma unroll
            for (int i = 0; i < 4; i++)
#pragma unroll
                for (int j = 0; j < 8; j++)
                    s[i][j] += q[i]*kv[j];
        }

        const float scale = 0.088388347648318447f;  // 1/sqrt(128)
#pragma unroll
        for (int i = 0; i < 4; i++)
#pragma unroll
            for (int j = 0; j < 8; j++) s[i][j] *= scale;

        if (!allones) {   // slow, faithful path (never taken for all-ones mask)
            for (int i = 0; i < 4; i++)
                for (int j = 0; j < 8; j++) {
                    int qr = q0 + ty*4 + i;
                    int kc = j0 + tx*8 + j;
                    if (mask[((size_t)b*SEQ + qr)*SEQ + kc] == 0) s[i][j] = -1e30f;
                }
        }

        // ---- online softmax (row spread over 8 consecutive lanes) ----
#pragma unroll
        for (int i = 0; i < 4; i++) {
            float rm = s[i][0];
#pragma unroll
            for (int j = 1; j < 8; j++) rm = fmaxf(rm, s[i][j]);
            rm = fmaxf(rm, __shfl_xor_sync(0xffffffffu, rm, 1));
            rm = fmaxf(rm, __shfl_xor_sync(0xffffffffu, rm, 2));
            rm = fmaxf(rm, __shfl_xor_sync(0xffffffffu, rm, 4));
            float mnew = fmaxf(m_i[i], rm);
            float corr = __expf(m_i[i] - mnew);
            float rs = 0.f;
#pragma unroll
            for (int j = 0; j < 8; j++) {
                float p = __expf(s[i][j] - mnew);
                sP[(ty*4+i)*PS + tx*8 + j] = p;
                rs += p;
            }
            rs += __shfl_xor_sync(0xffffffffu, rs, 1);
            rs += __shfl_xor_sync(0xffffffffu, rs, 2);
            rs += __shfl_xor_sync(0xffffffffu, rs, 4);
            m_i[i] = mnew;
            l_i[i] = l_i[i]*corr + rs;
#pragma unroll
            for (int c = 0; c < 16; c++) acc[i][c] *= corr;
        }
        __syncthreads();

        // ---- PV: O += P @ V ----
#pragma unroll 4
        for (int kk = 0; kk < BKV; kk++) {
            float pr[4];
#pragma unroll
            for (int i = 0; i < 4; i++) pr[i] = sP[(ty*4+i)*PS + kk];
            float vv[16];
            *(float4*)&vv[0]  = *(const float4*)&sV[kk*HD + tx*16];
            *(float4*)&vv[4]  = *(const float4*)&sV[kk*HD + tx*16 + 4];
            *(float4*)&vv[8]  = *(const float4*)&sV[kk*HD + tx*16 + 8];
            *(float4*)&vv[12] = *(const float4*)&sV[kk*HD + tx*16 + 12];
#pragma unroll
            for (int i = 0; i < 4; i++)
#pragma unroll
                for (int c = 0; c < 16; c++)
                    acc[i][c] += pr[i]*vv[c];
        }
    }

    // ---- epilogue: normalize, store to (B,S,H*D) ----
#pragma unroll
    for (int i = 0; i < 4; i++) {
        float inv = 1.f / l_i[i];
        int r = q0 + ty*4 + i;
        float* o = &g_A[((size_t)(b*SEQ + r))*HID + h*HD + tx*16];
        float t[16];
#pragma unroll
        for (int c = 0; c < 16; c++) t[c] = acc[i][c]*inv;
        *(float4*)&o[0]  = *(float4*)&t[0];
        *(float4*)&o[4]  = *(float4*)&t[4];
        *(float4*)&o[8]  = *(float4*)&t[8];
        *(float4*)&o[12] = *(float4*)&t[12];
    }
}

// ---------------- launch ----------------
extern "C" void kernel_launch(void* const* d_in, const int* in_sizes, int n_in,
                              void* d_out, int out_size)
{
    const float* X  = (const float*)d_in[0];
    const int* mask = (const int*)  d_in[1];
    const float* Wq = (const float*)d_in[2];
    const float* bq = (const float*)d_in[3];
    const float* Wk = (const float*)d_in[4];
    const float* bk = (const float*)d_in[5];
    const float* Wv = (const float*)d_in[6];
    const float* bv = (const float*)d_in[7];
    const float* Wo = (const float*)d_in[8];
    const float* bo = (const float*)d_in[9];
    float* out = (float*)d_out;

    float *qp, *kp, *vp, *ap;
    cudaGetSymbolAddress((void**)&qp, g_Q);
    cudaGetSymbolAddress((void**)&kp, g_K);
    cudaGetSymbolAddress((void**)&vp, g_V);
    cudaGetSymbolAddress((void**)&ap, g_A);

    cudaFuncSetAttribute(attn_kernel,
                         cudaFuncAttributeMaxDynamicSharedMemorySize,
                         ATTN_SMEM_BYTES);

    flag_init_kernel<<<1, 1>>>();
    mask_scan_kernel<<<1024, 256>>>(mask);

    dim3 gq(HID/128, MTOT/128);          // (16, 32)
    sgemm_bias_kernel<<<gq, 256>>>(X, Wq, bq, qp, MTOT, HID, HID);

    dim3 gkv(1, MTOT/128);               // (1, 32)
    sgemm_bias_kernel<<<gkv, 256>>>(X, Wk, bk, kp, MTOT, HD, HID);
    sgemm_bias_kernel<<<gkv, 256>>>(X, Wv, bv, vp, MTOT, HD, HID);

    dim3 ga(SEQ/BQ, NH, BATCH);          // (32, 16, 2)
    attn_kernel<<<ga, 128, ATTN_SMEM_BYTES>>>(mask);

    sgemm_bias_kernel<<<gq, 256>>>(ap, Wo, bo, out, MTOT, HID, HID);
}

// round 3
// speedup vs baseline: 1.7940x; 1.7940x over previous
#include <cuda_runtime.h>
#include <cuda_bf16.h>
#include <cstdint>
#include <math.h>

#define BATCH 2
#define SEQ   2048
#define HID   2048
#define NH    16
#define HD    128
#define MTOT  (BATCH*SEQ)

// ---------------- attention tile config ----------------
#define BQ    64
#define BKV   64
#define QKS   68      // padded stride for d-major Q/K smem tiles
#define VS    132     // padded stride for V tile
#define PS    65      // padded stride for P tile
#define ATTN_SMEM_FLOATS (128*QKS*2 + BKV*VS + BQ*PS)
#define ATTN_SMEM_BYTES  (ATTN_SMEM_FLOATS*4)

// ---------------- mma GEMM config ----------------
#define CHUNK_BYTES 65536           // 4 tiles x 128rows x 128B (Ahi,Alo,Bhi,Blo)
#define GEMM_DYN    (2*CHUNK_BYTES + 1024)

// ---------------- device scratch ----------------
__device__ float g_Q[(size_t)MTOT*HID];
__device__ float g_K[(size_t)MTOT*HD];
__device__ float g_V[(size_t)MTOT*HD];
__device__ float g_A[(size_t)MTOT*HID];
__device__ int   g_allones;

__device__ __nv_bfloat16 g_Xhi[(size_t)MTOT*HID];
__device__ __nv_bfloat16 g_Xlo[(size_t)MTOT*HID];
__device__ __nv_bfloat16 g_Ahi[(size_t)MTOT*HID];
__device__ __nv_bfloat16 g_Alo[(size_t)MTOT*HID];
__device__ __nv_bfloat16 g_WqTh[(size_t)HID*HID];
__device__ __nv_bfloat16 g_WqTl[(size_t)HID*HID];
__device__ __nv_bfloat16 g_WoTh[(size_t)HID*HID];
__device__ __nv_bfloat16 g_WoTl[(size_t)HID*HID];
__device__ __nv_bfloat16 g_WkTh[(size_t)HD*HID];
__device__ __nv_bfloat16 g_WkTl[(size_t)HD*HID];
__device__ __nv_bfloat16 g_WvTh[(size_t)HD*HID];
__device__ __nv_bfloat16 g_WvTl[(size_t)HD*HID];

// ---------------- helpers ----------------
__device__ __forceinline__ uint32_t smem_u32(const void* p) {
    uint32_t a;
    asm("{ .reg .u64 t; cvta.to.shared.u64 t, %1; cvt.u32.u64 %0, t; }" : "=r"(a) : "l"(p));
    return a;
}
__device__ __forceinline__ void cp16(uint32_t dst, const void* src) {
    asm volatile("cp.async.cg.shared.global [%0], [%1], 16;" :: "r"(dst), "l"(src));
}
__device__ __forceinline__ void ldsm4(uint32_t* r, uint32_t addr) {
    asm volatile("ldmatrix.sync.aligned.m8n8.x4.shared.b16 {%0,%1,%2,%3}, [%4];"
                 : "=r"(r[0]), "=r"(r[1]), "=r"(r[2]), "=r"(r[3]) : "r"(addr));
}
__device__ __forceinline__ void mma16816(float* c, const uint32_t* a, const uint32_t* b) {
    asm volatile(
        "mma.sync.aligned.m16n8k16.row.col.f32.bf16.bf16.f32 "
        "{%0,%1,%2,%3}, {%4,%5,%6,%7}, {%8,%9}, {%0,%1,%2,%3};"
        : "+f"(c[0]), "+f"(c[1]), "+f"(c[2]), "+f"(c[3])
        : "r"(a[0]), "r"(a[1]), "r"(a[2]), "r"(a[3]), "r"(b[0]), "r"(b[1]));
}
#define SW128(x) ((x) ^ (((x) >> 3) & 0x70))

// ---------------- mask pre-scan ----------------
__global__ void flag_init_kernel() { g_allones = 1; }

__global__ void mask_scan_kernel(const int* __restrict__ mask) {
    const int4* m4 = (const int4*)mask;
    const int total = BATCH*SEQ*SEQ/4;
    int bad = 0;
    for (int i = blockIdx.x*blockDim.x + threadIdx.x; i < total;
         i += gridDim.x*blockDim.x) {
        int4 v = m4[i];
        if ((v.x == 0) | (v.y == 0) | (v.z == 0) | (v.w == 0)) bad = 1;
    }
    if (bad) g_allones = 0;
}

// ---------------- fp32 -> bf16 hi/lo split (elementwise) ----------------
__global__ void split_kernel(const float* __restrict__ x,
                             __nv_bfloat16* __restrict__ hi,
                             __nv_bfloat16* __restrict__ lo, int n4) {
    for (int i = blockIdx.x*blockDim.x + threadIdx.x; i < n4;
         i += gridDim.x*blockDim.x) {
        float4 v = ((const float4*)x)[i];
        __nv_bfloat16 h0 = __float2bfloat16(v.x);
        __nv_bfloat16 h1 = __float2bfloat16(v.y);
        __nv_bfloat16 h2 = __float2bfloat16(v.z);
        __nv_bfloat16 h3 = __float2bfloat16(v.w);
        __nv_bfloat162* hp = (__nv_bfloat162*)hi;
        __nv_bfloat162* lp = (__nv_bfloat162*)lo;
        hp[i*2+0] = __nv_bfloat162(h0, h1);
        hp[i*2+1] = __nv_bfloat162(h2, h3);
        lp[i*2+0] = __nv_bfloat162(__float2bfloat16(v.x - __bfloat162float(h0)),
                                   __float2bfloat16(v.y - __bfloat162float(h1)));
        lp[i*2+1] = __nv_bfloat162(__float2bfloat16(v.z - __bfloat162float(h2)),
                                   __float2bfloat16(v.w - __bfloat162float(h3)));
    }
}

// ---------------- W[K,N] -> WT[N,K] bf16 hi/lo transpose-split ----------------
__global__ void tsplit_kernel(const float* __restrict__ W,
                              __nv_bfloat16* __restrict__ Th,
                              __nv_bfloat16* __restrict__ Tl, int K, int N) {
    __shared__ float t[32][33];
    int x = blockIdx.x*32 + threadIdx.x;             // n index
#pragma unroll
    for (int j = 0; j < 4; j++) {
        int y = blockIdx.y*32 + threadIdx.y + j*8;   // k index
        t[threadIdx.y + j*8][threadIdx.x] = W[(size_t)y*N + x];
    }
    __syncthreads();
    int xo = blockIdx.y*32 + threadIdx.x;            // k index (output col)
#pragma unroll
    for (int j = 0; j < 4; j++) {
        int yo = blockIdx.x*32 + threadIdx.y + j*8;  // n index (output row)
        float v = t[threadIdx.x][threadIdx.y + j*8];
        __nv_bfloat16 h = __float2bfloat16(v);
        Th[(size_t)yo*K + xo] = h;
        Tl[(size_t)yo*K + xo] = __float2bfloat16(v - __bfloat162float(h));
    }
}

// ---------------- mma.sync bf16-split GEMM ----------------
// C[M,N] = Ahi@Bhi^T + Ahi@Blo^T + Alo@Bhi^T + bias ; A[M,K], B[N,K] both K-major.
// 128x128 block tile, 8 warps (2 m-groups x 4 n-groups), warp tile 64x32.
__global__ __launch_bounds__(256) void gemm_mma_kernel(
    const __nv_bfloat16* __restrict__ Ahi, const __nv_bfloat16* __restrict__ Alo,
    const __nv_bfloat16* __restrict__ Bhi, const __nv_bfloat16* __restrict__ Blo,
    const float* __restrict__ bias, float* __restrict__ C,
    int M, int N, int K)
{
    extern __shared__ char dyn[];
    const int tid  = threadIdx.x;
    const int warp = tid >> 5;
    const int lane = tid & 31;
    const int wm   = warp >> 2;        // 0..1
    const int wn   = warp & 3;         // 0..3
    const int n0 = blockIdx.x * 128;
    const int m0 = blockIdx.y * 128;

    const uint32_t sbase = (smem_u32(dyn) + 127u) & ~127u;

    float acc[4][4][4];
#pragma unroll
    for (int mt = 0; mt < 4; mt++)
#pragma unroll
        for (int nt = 0; nt < 4; nt++)
#pragma unroll
            for (int q = 0; q < 4; q++) acc[mt][nt][q] = 0.f;

    auto stage = [&](uint32_t tb, int k0) {
        const uint32_t tA_h = tb, tA_l = tb + 16384, tB_h = tb + 32768, tB_l = tb + 49152;
#pragma unroll
        for (int u = tid; u < 4096; u += 256) {
            int t   = u >> 10;
            int idx = u & 1023;
            int row = idx >> 3;
            int c16 = idx & 7;
            const __nv_bfloat16* src;
            uint32_t tbase;
            if (t == 0)      { src = Ahi + (size_t)(m0+row)*K + k0 + c16*8; tbase = tA_h; }
            else if (t == 1) { src = Alo + (size_t)(m0+row)*K + k0 + c16*8; tbase = tA_l; }
            else if (t == 2) { src = Bhi + (size_t)(n0+row)*K + k0 + c16*8; tbase = tB_h; }
            else             { src = Blo + (size_t)(n0+row)*K + k0 + c16*8; tbase = tB_l; }
            cp16(tbase + SW128((uint32_t)(row*128 + c16*16)), src);
        }
        asm volatile("cp.async.commit_group;" ::: "memory");
    };

    const int nch = K / 64;
    stage(sbase, 0);

    for (int ch = 0; ch < nch; ch++) {
        if (ch + 1 < nch) {
            stage(sbase + ((ch+1)&1)*CHUNK_BYTES, (ch+1)*64);
            asm volatile("cp.async.wait_group 1;" ::: "memory");
        } else {
            asm volatile("cp.async.wait_group 0;" ::: "memory");
        }
        __syncthreads();

        const uint32_t tb   = sbase + (ch&1)*CHUNK_BYTES;
        const uint32_t tAhi = tb, tAlo = tb + 16384, tBhi = tb + 32768, tBlo = tb + 49152;

#pragma unroll
        for (int ks = 0; ks < 4; ks++) {
            uint32_t ah[4][4], al[4][4], bh[2][4], bl[2][4];
            const uint32_t abyte = (uint32_t)(ks*32 + (lane>>4)*16);
            const int      arow  = wm*64 + (lane & 15);
#pragma unroll
            for (int mt = 0; mt < 4; mt++) {
                uint32_t off = SW128((uint32_t)((arow + mt*16)*128) + abyte);
                ldsm4(ah[mt], tAhi + off);
                ldsm4(al[mt], tAlo + off);
            }
            const uint32_t bbyte = (uint32_t)(ks*32 + ((lane>>3)&1)*16);
            const int      brow  = wn*32 + (lane & 7) + (lane>>4)*8;
#pragma unroll
            for (int np = 0; np < 2; np++) {
                uint32_t off = SW128((uint32_t)((brow + np*16)*128) + bbyte);
                ldsm4(bh[np], tBhi + off);
                ldsm4(bl[np], tBlo + off);
            }
#pragma unroll
            for (int mt = 0; mt < 4; mt++)
#pragma unroll
                for (int nt = 0; nt < 4; nt++) {
                    const uint32_t* bph = &bh[nt>>1][(nt&1)*2];
                    const uint32_t* bpl = &bl[nt>>1][(nt&1)*2];
                    mma16816(acc[mt][nt], ah[mt], bph);
                    mma16816(acc[mt][nt], ah[mt], bpl);
                    mma16816(acc[mt][nt], al[mt], bph);
                }
        }
        __syncthreads();
    }

    // epilogue: direct store + bias
    const int g  = lane >> 2;
    const int tg = lane & 3;
#pragma unroll
    for (int mt = 0; mt < 4; mt++) {
        const int r0 = m0 + wm*64 + mt*16 + g;
#pragma unroll
        for (int nt = 0; nt < 4; nt++) {
            const int col = n0 + wn*32 + nt*8 + tg*2;
            const float b0 = bias[col], b1 = bias[col+1];
            float2 v0 = make_float2(acc[mt][nt][0] + b0, acc[mt][nt][1] + b1);
            float2 v1 = make_float2(acc[mt][nt][2] + b0, acc[mt][nt][3] + b1);
            *(float2*)&C[(size_t)r0*N + col]     = v0;
            *(float2*)&C[(size_t)(r0+8)*N + col] = v1;
        }
    }
}

// ---------------- flash attention (fp32, online softmax, 256 threads) ----------------
// grid (SEQ/BQ, NH, BATCH); thread (ty=tid/8 in 0..31, tx=tid%8):
// rows ty*2+i (i<2); score cols tx*8+j (j<8); O cols grp*32 + tx*4 + j (grp<4, j<4).
__global__ __launch_bounds__(256) void attn_kernel(const int* __restrict__ mask)
{
    extern __shared__ float sm[];
    float* sQt = sm;                    // [128][QKS] d-major
    float* sKt = sQt + 128*QKS;         // [128][QKS] d-major
    float* sV  = sKt + 128*QKS;         // [BKV][VS]  row-major padded
    float* sP  = sV  + BKV*VS;          // [BQ][PS]

    const int qb  = blockIdx.x;
    const int h   = blockIdx.y;
    const int b   = blockIdx.z;
    const int tid = threadIdx.x;
    const int tx  = tid & 7;
    const int ty  = tid >> 3;           // 0..31
    const int q0  = qb * BQ;
    const int allones = g_allones;
    const int dstag = tx >> 2;          // bank-stagger for K-tile reads

    for (int e = tid; e < BQ*32; e += 256) {
        int r  = e & 63;
        int c4 = e >> 6;
        float4 v = *(const float4*)&g_Q[((size_t)(b*SEQ + q0 + r))*HID + h*HD + c4*4];
        int d = c4*4;
        sQt[(d+0)*QKS + r] = v.x;
        sQt[(d+1)*QKS + r] = v.y;
        sQt[(d+2)*QKS + r] = v.z;
        sQt[(d+3)*QKS + r] = v.w;
    }

    float m_i[2], l_i[2], acc[2][16];
#pragma unroll
    for (int i = 0; i < 2; i++) {
        m_i[i] = -1e30f;
        l_i[i] = 0.f;
#pragma unroll
        for (int c = 0; c < 16; c++) acc[i][c] = 0.f;
    }

    for (int j0 = 0; j0 < SEQ; j0 += BKV) {
        __syncthreads();
        for (int e = tid; e < BKV*32; e += 256) {
            int r  = e & 63;
            int c4 = e >> 6;
            float4 v = *(const float4*)&g_K[((size_t)(b*SEQ + j0 + r))*HD + c4*4];
            int d = c4*4;
            sKt[(d+0)*QKS + r] = v.x;
            sKt[(d+1)*QKS + r] = v.y;
            sKt[(d+2)*QKS + r] = v.z;
            sKt[(d+3)*QKS + r] = v.w;
        }
        for (int e = tid; e < BKV*32; e += 256) {
            int r  = e & 63;
            int c4 = e >> 6;
            float4 v = *(const float4*)&g_V[((size_t)(b*SEQ + j0 + r))*HD + c4*4];
            *(float4*)&sV[r*VS + c4*4] = v;
        }
        __syncthreads();

        float s[2][8];
#pragma unroll
        for (int i = 0; i < 2; i++)
#pragma unroll
            for (int j = 0; j < 8; j++) s[i][j] = 0.f;

#pragma unroll 4
        for (int d0 = 0; d0 < HD; d0++) {
            int dt = (d0 + dstag) & (HD-1);
            float2 qv = *(const float2*)&sQt[dt*QKS + ty*2];
            float4 k0 = *(const float4*)&sKt[dt*QKS + tx*8];
            float4 k1 = *(const float4*)&sKt[dt*QKS + tx*8 + 4];
            float q[2]  = {qv.x, qv.y};
            float kv[8] = {k0.x,k0.y,k0.z,k0.w,k1.x,k1.y,k1.z,k1.w};
#pragma unroll
            for (int i = 0; i < 2; i++)
#pragma unroll
                for (int j = 0; j < 8; j++)
                    s[i][j] += q[i]*kv[j];
        }

        const float scale = 0.088388347648318447f;  // 1/sqrt(128)
#pragma unroll
        for (int i = 0; i < 2; i++)
#pragma unroll
            for (int j = 0; j < 8; j++) s[i][j] *= scale;

        if (!allones) {
            for (int i = 0; i < 2; i++)
                for (int j = 0; j < 8; j++) {
                    int qr = q0 + ty*2 + i;
                    int kc = j0 + tx*8 + j;
                    if (mask[((size_t)b*SEQ + qr)*SEQ + kc] == 0) s[i][j] = -1e30f;
                }
        }

#pragma unroll
        for (int i = 0; i < 2; i++) {
            float rm = s[i][0];
#pragma unroll
            for (int j = 1; j < 8; j++) rm = fmaxf(rm, s[i][j]);
            rm = fmaxf(rm, __shfl_xor_sync(0xffffffffu, rm, 1));
            rm = fmaxf(rm, __shfl_xor_sync(0xffffffffu, rm, 2));
            rm = fmaxf(rm, __shfl_xor_sync(0xffffffffu, rm, 4));
            float mnew = fmaxf(m_i[i], rm);
            float corr = __expf(m_i[i] - mnew);
            float rs = 0.f;
#pragma unroll
            for (int j = 0; j < 8; j++) {
                float p = __expf(s[i][j] - mnew);
                sP[(ty*2+i)*PS + tx*8 + j] = p;
                rs += p;
            }
            rs += __shfl_xor_sync(0xffffffffu, rs, 1);
            rs += __shfl_xor_sync(0xffffffffu, rs, 2);
            rs += __shfl_xor_sync(0xffffffffu, rs, 4);
            m_i[i] = mnew;
            l_i[i] = l_i[i]*corr + rs;
#pragma unroll
            for (int c = 0; c < 16; c++) acc[i][c] *= corr;
        }
        __syncthreads();

#pragma unroll 4
        for (int kk = 0; kk < BKV; kk++) {
            float pr[2];
            pr[0] = sP[(ty*2+0)*PS + kk];
            pr[1] = sP[(ty*2+1)*PS + kk];
            float vv[16];
#pragma unroll
            for (int grp = 0; grp < 4; grp++)
                *(float4*)&vv[grp*4] = *(const float4*)&sV[kk*VS + grp*32 + tx*4];
#pragma unroll
            for (int i = 0; i < 2; i++)
#pragma unroll
                for (int c = 0; c < 16; c++)
                    acc[i][c] += pr[i]*vv[c];
        }
    }

#pragma unroll
    for (int i = 0; i < 2; i++) {
        float inv = 1.f / l_i[i];
        int r = q0 + ty*2 + i;
#pragma unroll
        for (int grp = 0; grp < 4; grp++) {
            float4 o;
            o.x = acc[i][grp*4+0]*inv;
            o.y = acc[i][grp*4+1]*inv;
            o.z = acc[i][grp*4+2]*inv;
            o.w = acc[i][grp*4+3]*inv;
            *(float4*)&g_A[((size_t)(b*SEQ + r))*HID + h*HD + grp*32 + tx*4] = o;
        }
    }
}

// ---------------- launch ----------------
extern "C" void kernel_launch(void* const* d_in, const int* in_sizes, int n_in,
                              void* d_out, int out_size)
{
    const float* X  = (const float*)d_in[0];
    const int* mask = (const int*)  d_in[1];
    const float* Wq = (const float*)d_in[2];
    const float* bq = (const float*)d_in[3];
    const float* Wk = (const float*)d_in[4];
    const float* bk = (const float*)d_in[5];
    const float* Wv = (const float*)d_in[6];
    const float* bv = (const float*)d_in[7];
    const float* Wo = (const float*)d_in[8];
    const float* bo = (const float*)d_in[9];
    float* out = (float*)d_out;

    float *qp, *kp, *vp, *ap;
    cudaGetSymbolAddress((void**)&qp, g_Q);
    cudaGetSymbolAddress((void**)&kp, g_K);
    cudaGetSymbolAddress((void**)&vp, g_V);
    cudaGetSymbolAddress((void**)&ap, g_A);

    __nv_bfloat16 *xh, *xl, *ah, *al, *wqh, *wql, *woh, *wol, *wkh, *wkl, *wvh, *wvl;
    cudaGetSymbolAddress((void**)&xh,  g_Xhi);  cudaGetSymbolAddress((void**)&xl,  g_Xlo);
    cudaGetSymbolAddress((void**)&ah,  g_Ahi);  cudaGetSymbolAddress((void**)&al,  g_Alo);
    cudaGetSymbolAddress((void**)&wqh, g_WqTh); cudaGetSymbolAddress((void**)&wql, g_WqTl);
    cudaGetSymbolAddress((void**)&woh, g_WoTh); cudaGetSymbolAddress((void**)&wol, g_WoTl);
    cudaGetSymbolAddress((void**)&wkh, g_WkTh); cudaGetSymbolAddress((void**)&wkl, g_WkTl);
    cudaGetSymbolAddress((void**)&wvh, g_WvTh); cudaGetSymbolAddress((void**)&wvl, g_WvTl);

    cudaFuncSetAttribute(attn_kernel, cudaFuncAttributeMaxDynamicSharedMemorySize,
                         ATTN_SMEM_BYTES);
    cudaFuncSetAttribute(gemm_mma_kernel, cudaFuncAttributeMaxDynamicSharedMemorySize,
                         GEMM_DYN);

    flag_init_kernel<<<1, 1>>>();
    mask_scan_kernel<<<512, 256>>>(mask);

    split_kernel<<<4096, 256>>>(X, xh, xl, MTOT*HID/4);
    tsplit_kernel<<<dim3(HID/32, HID/32), dim3(32,8)>>>(Wq, wqh, wql, HID, HID);
    tsplit_kernel<<<dim3(HD/32,  HID/32), dim3(32,8)>>>(Wk, wkh, wkl, HID, HD);
    tsplit_kernel<<<dim3(HD/32,  HID/32), dim3(32,8)>>>(Wv, wvh, wvl, HID, HD);
    tsplit_kernel<<<dim3(HID/32, HID/32), dim3(32,8)>>>(Wo, woh, wol, HID, HID);

    gemm_mma_kernel<<<dim3(HID/128, MTOT/128), 256, GEMM_DYN>>>(
        xh, xl, wqh, wql, bq, qp, MTOT, HID, HID);
    gemm_mma_kernel<<<dim3(1, MTOT/128), 256, GEMM_DYN>>>(
        xh, xl, wkh, wkl, bk, kp, MTOT, HD, HID);
    gemm_mma_kernel<<<dim3(1, MTOT/128), 256, GEMM_DYN>>>(
        xh, xl, wvh, wvl, bv, vp, MTOT, HD, HID);

    attn_kernel<<<dim3(SEQ/BQ, NH, BATCH), 256, ATTN_SMEM_BYTES>>>(mask);

    split_kernel<<<4096, 256>>>(ap, ah, al, MTOT*HID/4);
    gemm_mma_kernel<<<dim3(HID/128, MTOT/128), 256, GEMM_DYN>>>(
        ah, al, woh, wol, bo, out, MTOT, HID, HID);
}

// round 5
// speedup vs baseline: 5.2464x; 2.9244x over previous
#include <cuda_runtime.h>
#include <cuda_bf16.h>
#include <cstdint>
#include <math.h>

#define BATCH 2
#define SEQ   2048
#define HID   2048
#define NH    16
#define HD    128
#define MTOT  (BATCH*SEQ)

// ---------------- mma GEMM config ----------------
#define CHUNK_BYTES 65536           // 4 tiles x 128rows x 128B (Ahi,Alo,Bhi,Blo)
#define GEMM_DYN    (2*CHUNK_BYTES + 1024)

// ---------------- mma attention config ----------------
#define BKV 64
#define ATTN_DYN (3*65536 + 1024)   // Q(64KB) + 2 KV buffers(64KB each) + align

// ---------------- device scratch ----------------
__device__ float g_K[(size_t)MTOT*HD];
__device__ float g_V[(size_t)MTOT*HD];
__device__ int   g_allones;

__device__ __nv_bfloat16 g_Xhi[(size_t)MTOT*HID];
__device__ __nv_bfloat16 g_Xlo[(size_t)MTOT*HID];
__device__ __nv_bfloat16 g_Qhi[(size_t)MTOT*HID];
__device__ __nv_bfloat16 g_Qlo[(size_t)MTOT*HID];
__device__ __nv_bfloat16 g_Ahi[(size_t)MTOT*HID];
__device__ __nv_bfloat16 g_Alo[(size_t)MTOT*HID];
__device__ __nv_bfloat16 g_Khi[(size_t)MTOT*HD];
__device__ __nv_bfloat16 g_Klo[(size_t)MTOT*HD];
__device__ __nv_bfloat16 g_VTh[(size_t)BATCH*HD*SEQ];
__device__ __nv_bfloat16 g_VTl[(size_t)BATCH*HD*SEQ];
__device__ __nv_bfloat16 g_WqTh[(size_t)HID*HID];
__device__ __nv_bfloat16 g_WqTl[(size_t)HID*HID];
__device__ __nv_bfloat16 g_WoTh[(size_t)HID*HID];
__device__ __nv_bfloat16 g_WoTl[(size_t)HID*HID];
__device__ __nv_bfloat16 g_WkTh[(size_t)HD*HID];
__device__ __nv_bfloat16 g_WkTl[(size_t)HD*HID];
__device__ __nv_bfloat16 g_WvTh[(size_t)HD*HID];
__device__ __nv_bfloat16 g_WvTl[(size_t)HD*HID];

// ---------------- helpers ----------------
__device__ __forceinline__ uint32_t smem_u32(const void* p) {
    uint32_t a;
    asm("{ .reg .u64 t; cvta.to.shared.u64 t, %1; cvt.u32.u64 %0, t; }" : "=r"(a) : "l"(p));
    return a;
}
__device__ __forceinline__ void cp16(uint32_t dst, const void* src) {
    asm volatile("cp.async.cg.shared.global [%0], [%1], 16;" :: "r"(dst), "l"(src));
}
__device__ __forceinline__ void ldsm4(uint32_t* r, uint32_t addr) {
    asm volatile("ldmatrix.sync.aligned.m8n8.x4.shared.b16 {%0,%1,%2,%3}, [%4];"
                 : "=r"(r[0]), "=r"(r[1]), "=r"(r[2]), "=r"(r[3]) : "r"(addr));
}
__device__ __forceinline__ void mma16816(float* c, const uint32_t* a, const uint32_t* b) {
    asm volatile(
        "mma.sync.aligned.m16n8k16.row.col.f32.bf16.bf16.f32 "
        "{%0,%1,%2,%3}, {%4,%5,%6,%7}, {%8,%9}, {%0,%1,%2,%3};"
        : "+f"(c[0]), "+f"(c[1]), "+f"(c[2]), "+f"(c[3])
        : "r"(a[0]), "r"(a[1]), "r"(a[2]), "r"(a[3]), "r"(b[0]), "r"(b[1]));
}
// packed {lo, hi} bf16x2
__device__ __forceinline__ uint32_t pack_bf16(float lo, float hi) {
    uint32_t r;
    asm("cvt.rn.bf16x2.f32 %0, %1, %2;" : "=r"(r) : "f"(hi), "f"(lo));
    return r;
}
#define SW128(x) ((x) ^ (((x) >> 3) & 0x70))

// ---------------- mask pre-scan ----------------
__global__ void flag_init_kernel() { g_allones = 1; }

__global__ void mask_scan_kernel(const int* __restrict__ mask) {
    const int4* m4 = (const int4*)mask;
    const int total = BATCH*SEQ*SEQ/4;
    int bad = 0;
    for (int i = blockIdx.x*blockDim.x + threadIdx.x; i < total;
         i += gridDim.x*blockDim.x) {
        int4 v = m4[i];
        if ((v.x == 0) | (v.y == 0) | (v.z == 0) | (v.w == 0)) bad = 1;
    }
    if (bad) g_allones = 0;
}

// ---------------- fp32 -> bf16 hi/lo split (elementwise) ----------------
__global__ void split_kernel(const float* __restrict__ x,
                             __nv_bfloat16* __restrict__ hi,
                             __nv_bfloat16* __restrict__ lo, int n4) {
    for (int i = blockIdx.x*blockDim.x + threadIdx.x; i < n4;
         i += gridDim.x*blockDim.x) {
        float4 v = ((const float4*)x)[i];
        __nv_bfloat16 h0 = __float2bfloat16(v.x);
        __nv_bfloat16 h1 = __float2bfloat16(v.y);
        __nv_bfloat16 h2 = __float2bfloat16(v.z);
        __nv_bfloat16 h3 = __float2bfloat16(v.w);
        __nv_bfloat162* hp = (__nv_bfloat162*)hi;
        __nv_bfloat162* lp = (__nv_bfloat162*)lo;
        hp[i*2+0] = __nv_bfloat162(h0, h1);
        hp[i*2+1] = __nv_bfloat162(h2, h3);
        lp[i*2+0] = __nv_bfloat162(__float2bfloat16(v.x - __bfloat162float(h0)),
                                   __float2bfloat16(v.y - __bfloat162float(h1)));
        lp[i*2+1] = __nv_bfloat162(__float2bfloat16(v.z - __bfloat162float(h2)),
                                   __float2bfloat16(v.w - __bfloat162float(h3)));
    }
}

// ---------------- W[K,N] -> WT[N,K] bf16 hi/lo transpose-split ----------------
__global__ void tsplit_kernel(const float* __restrict__ W,
                              __nv_bfloat16* __restrict__ Th,
                              __nv_bfloat16* __restrict__ Tl, int K, int N) {
    __shared__ float t[32][33];
    int x = blockIdx.x*32 + threadIdx.x;
#pragma unroll
    for (int j = 0; j < 4; j++) {
        int y = blockIdx.y*32 + threadIdx.y + j*8;
        t[threadIdx.y + j*8][threadIdx.x] = W[(size_t)y*N + x];
    }
    __syncthreads();
    int xo = blockIdx.y*32 + threadIdx.x;
#pragma unroll
    for (int j = 0; j < 4; j++) {
        int yo = blockIdx.x*32 + threadIdx.y + j*8;
        float v = t[threadIdx.x][threadIdx.y + j*8];
        __nv_bfloat16 h = __float2bfloat16(v);
        Th[(size_t)yo*K + xo] = h;
        Tl[(size_t)yo*K + xo] = __float2bfloat16(v - __bfloat162float(h));
    }
}

// ---------------- V[B*S,D] -> VT[b][d][s] bf16 hi/lo transpose-split ----------------
__global__ void vtsplit_kernel(const float* __restrict__ V,
                               __nv_bfloat16* __restrict__ Th,
                               __nv_bfloat16* __restrict__ Tl) {
    __shared__ float t[32][33];
    int b  = blockIdx.z;
    int s0 = blockIdx.x*32;
    int d0 = blockIdx.y*32;
#pragma unroll
    for (int j = 0; j < 4; j++) {
        int s = s0 + threadIdx.y + j*8;
        t[threadIdx.y + j*8][threadIdx.x] = V[((size_t)b*SEQ + s)*HD + d0 + threadIdx.x];
    }
    __syncthreads();
#pragma unroll
    for (int j = 0; j < 4; j++) {
        int d = d0 + threadIdx.y + j*8;
        float v = t[threadIdx.x][threadIdx.y + j*8];
        __nv_bfloat16 h = __float2bfloat16(v);
        size_t o = ((size_t)b*HD + d)*SEQ + s0 + threadIdx.x;
        Th[o] = h;
        Tl[o] = __float2bfloat16(v - __bfloat162float(h));
    }
}

// ---------------- mma.sync bf16-split GEMM ----------------
// C[M,N] = Ahi@Bhi^T + Ahi@Blo^T + Alo@Bhi^T + bias ; A[M,K], B[N,K] K-major.
// SPLITOUT: write ((acc+bias)*oscale) as bf16 hi/lo pair instead of fp32.
template<bool SPLITOUT>
__global__ __launch_bounds__(256) void gemm_mma_kernel(
    const __nv_bfloat16* __restrict__ Ahi, const __nv_bfloat16* __restrict__ Alo,
    const __nv_bfloat16* __restrict__ Bhi, const __nv_bfloat16* __restrict__ Blo,
    const float* __restrict__ bias, float* __restrict__ C,
    __nv_bfloat16* __restrict__ Chi, __nv_bfloat16* __restrict__ Clo,
    float oscale, int M, int N, int K)
{
    extern __shared__ char dyn[];
    const int tid  = threadIdx.x;
    const int warp = tid >> 5;
    const int lane = tid & 31;
    const int wm   = warp >> 2;
    const int wn   = warp & 3;
    const int n0 = blockIdx.x * 128;
    const int m0 = blockIdx.y * 128;

    const uint32_t sbase = (smem_u32(dyn) + 1023u) & ~1023u;

    float acc[4][4][4];
#pragma unroll
    for (int mt = 0; mt < 4; mt++)
#pragma unroll
        for (int nt = 0; nt < 4; nt++)
#pragma unroll
            for (int q = 0; q < 4; q++) acc[mt][nt][q] = 0.f;

    auto stage = [&](uint32_t tb, int k0) {
        const uint32_t tA_h = tb, tA_l = tb + 16384, tB_h = tb + 32768, tB_l = tb + 49152;
#pragma unroll
        for (int u = tid; u < 4096; u += 256) {
            int t   = u >> 10;
            int idx = u & 1023;
            int row = idx >> 3;
            int c16 = idx & 7;
            const __nv_bfloat16* src;
            uint32_t tbase;
            if (t == 0)      { src = Ahi + (size_t)(m0+row)*K + k0 + c16*8; tbase = tA_h; }
            else if (t == 1) { src = Alo + (size_t)(m0+row)*K + k0 + c16*8; tbase = tA_l; }
            else if (t == 2) { src = Bhi + (size_t)(n0+row)*K + k0 + c16*8; tbase = tB_h; }
            else             { src = Blo + (size_t)(n0+row)*K + k0 + c16*8; tbase = tB_l; }
            cp16(tbase + SW128((uint32_t)(row*128 + c16*16)), src);
        }
        asm volatile("cp.async.commit_group;" ::: "memory");
    };

    const int nch = K / 64;
    stage(sbase, 0);

    for (int ch = 0; ch < nch; ch++) {
        if (ch + 1 < nch) {
            stage(sbase + ((ch+1)&1)*CHUNK_BYTES, (ch+1)*64);
            asm volatile("cp.async.wait_group 1;" ::: "memory");
        } else {
            asm volatile("cp.async.wait_group 0;" ::: "memory");
        }
        __syncthreads();

        const uint32_t tb   = sbase + (ch&1)*CHUNK_BYTES;
        const uint32_t tAhi = tb, tAlo = tb + 16384, tBhi = tb + 32768, tBlo = tb + 49152;

#pragma unroll
        for (int ks = 0; ks < 4; ks++) {
            uint32_t ah[4][4], al[4][4], bh[2][4], bl[2][4];
            const uint32_t abyte = (uint32_t)(ks*32 + (lane>>4)*16);
            const int      arow  = wm*64 + (lane & 15);
#pragma unroll
            for (int mt = 0; mt < 4; mt++) {
                uint32_t off = SW128((uint32_t)((arow + mt*16)*128) + abyte);
                ldsm4(ah[mt], tAhi + off);
                ldsm4(al[mt], tAlo + off);
            }
            const uint32_t bbyte = (uint32_t)(ks*32 + ((lane>>3)&1)*16);
            const int      brow  = wn*32 + (lane & 7) + (lane>>4)*8;
#pragma unroll
            for (int np = 0; np < 2; np++) {
                uint32_t off = SW128((uint32_t)((brow + np*16)*128) + bbyte);
                ldsm4(bh[np], tBhi + off);
                ldsm4(bl[np], tBlo + off);
            }
#pragma unroll
            for (int mt = 0; mt < 4; mt++)
#pragma unroll
                for (int nt = 0; nt < 4; nt++) {
                    const uint32_t* bph = &bh[nt>>1][(nt&1)*2];
                    const uint32_t* bpl = &bl[nt>>1][(nt&1)*2];
                    mma16816(acc[mt][nt], ah[mt], bph);
                    mma16816(acc[mt][nt], ah[mt], bpl);
                    mma16816(acc[mt][nt], al[mt], bph);
                }
        }
        __syncthreads();
    }

    const int g  = lane >> 2;
    const int tg = lane & 3;
#pragma unroll
    for (int mt = 0; mt < 4; mt++) {
        const int r0 = m0 + wm*64 + mt*16 + g;
#pragma unroll
        for (int nt = 0; nt < 4; nt++) {
            const int col = n0 + wn*32 + nt*8 + tg*2;
            const float b0 = bias[col], b1 = bias[col+1];
            if (SPLITOUT) {
                float v0 = (acc[mt][nt][0] + b0)*oscale;
                float v1 = (acc[mt][nt][1] + b1)*oscale;
                float v2 = (acc[mt][nt][2] + b0)*oscale;
                float v3 = (acc[mt][nt][3] + b1)*oscale;
                uint32_t h01 = pack_bf16(v0, v1);
                uint32_t h23 = pack_bf16(v2, v3);
                uint32_t l01 = pack_bf16(v0 - __uint_as_float(h01<<16),
                                         v1 - __uint_as_float(h01 & 0xffff0000u));
                uint32_t l23 = pack_bf16(v2 - __uint_as_float(h23<<16),
                                         v3 - __uint_as_float(h23 & 0xffff0000u));
                *(uint32_t*)&Chi[(size_t)r0*N + col]     = h01;
                *(uint32_t*)&Chi[(size_t)(r0+8)*N + col] = h23;
                *(uint32_t*)&Clo[(size_t)r0*N + col]     = l01;
                *(uint32_t*)&Clo[(size_t)(r0+8)*N + col] = l23;
            } else {
                float2 v0 = make_float2(acc[mt][nt][0] + b0, acc[mt][nt][1] + b1);
                float2 v1 = make_float2(acc[mt][nt][2] + b0, acc[mt][nt][3] + b1);
                *(float2*)&C[(size_t)r0*N + col]     = v0;
                *(float2*)&C[(size_t)(r0+8)*N + col] = v1;
            }
        }
    }
}

// ---------------- mma.sync flash attention ----------------
// grid (SEQ/128, NH, BATCH), 256 threads (8 warps x 16 q-rows).
// QK^T: A=Q[16,128] hi/lo, B=K[64,128] hi/lo (3-term split).
// P.V : A=P (from score C-fragments, split in registers), B=VT[128,64] hi/lo.
__global__ __launch_bounds__(256) void attn_mma_kernel(const int* __restrict__ mask)
{
    extern __shared__ char dyn[];
    const int tid  = threadIdx.x;
    const int warp = tid >> 5;
    const int lane = tid & 31;
    const int g    = lane >> 2;
    const int tg   = lane & 3;
    const int h  = blockIdx.y;
    const int b  = blockIdx.z;
    const int q0 = blockIdx.x * 128;
    const int allones = g_allones;

    const uint32_t base = (smem_u32(dyn) + 1023u) & ~1023u;
    const uint32_t sQ   = base;                 // Qhi: c0@0,c1@16384 ; Qlo @32768
    const uint32_t sKV0 = base + 65536;         // per buf: Kh(2x8KB), Kl, Vh(16KB), Vl

    // ---- stage Q (once) ----
    for (int u = tid; u < 4096; u += 256) {
        int t = u >> 11, idx = u & 2047;
        int chunk = idx >> 10, r = (idx >> 3) & 127, c16 = idx & 7;
        const __nv_bfloat16* src =
            (t ? g_Qlo : g_Qhi) + ((size_t)(b*SEQ + q0 + r))*HID + h*HD + chunk*64 + c16*8;
        cp16(sQ + t*32768 + chunk*16384 + SW128((uint32_t)(r*128 + c16*16)), src);
    }

    auto stageKV = [&](uint32_t bb, int j0) {
#pragma unroll
        for (int u = tid; u < 2048; u += 256) {   // K hi/lo
            int t = u >> 10, idx = u & 1023;
            int chunk = idx >> 9, r = (idx >> 3) & 63, c16 = idx & 7;
            const __nv_bfloat16* src =
                (t ? g_Klo : g_Khi) + ((size_t)(b*SEQ + j0 + r))*HD + chunk*64 + c16*8;
            cp16(bb + t*16384 + chunk*8192 + SW128((uint32_t)(r*128 + c16*16)), src);
        }
#pragma unroll
        for (int u = tid; u < 2048; u += 256) {   // VT hi/lo
            int t = u >> 10, idx = u & 1023;
            int r = idx >> 3, c16 = idx & 7;
            const __nv_bfloat16* src =
                (t ? g_VTl : g_VTh) + ((size_t)b*HD + r)*SEQ + j0 + c16*8;
            cp16(bb + 32768 + t*16384 + SW128((uint32_t)(r*128 + c16*16)), src);
        }
        asm volatile("cp.async.commit_group;" ::: "memory");
    };

    stageKV(sKV0, 0);

    float m0r = -1e30f, m1r = -1e30f, l0r = 0.f, l1r = 0.f;
    float o[16][4];
#pragma unroll
    for (int nt = 0; nt < 16; nt++)
#pragma unroll
        for (int e = 0; e < 4; e++) o[nt][e] = 0.f;

    const int NT = SEQ / BKV;
    for (int t = 0; t < NT; t++) {
        if (t + 1 < NT) {
            stageKV(sKV0 + ((t+1)&1)*65536, (t+1)*BKV);
            asm volatile("cp.async.wait_group 1;" ::: "memory");
        } else {
            asm volatile("cp.async.wait_group 0;" ::: "memory");
        }
        __syncthreads();

        const uint32_t bb = sKV0 + (t&1)*65536;
        const uint32_t kh = bb, kl = bb + 16384, vh = bb + 32768, vl = bb + 49152;
        const int j0 = t * BKV;

        // ---- scores S[16, 64] ----
        float s[8][4];
#pragma unroll
        for (int nt = 0; nt < 8; nt++)
#pragma unroll
            for (int e = 0; e < 4; e++) s[nt][e] = 0.f;

#pragma unroll
        for (int ks = 0; ks < 8; ks++) {
            uint32_t aH[4], aL[4];
            uint32_t aoff = (ks>>2)*16384 +
                SW128((uint32_t)((warp*16 + (lane & 15))*128 + (ks&3)*32 + (lane>>4)*16));
            ldsm4(aH, sQ + aoff);
            ldsm4(aL, sQ + 32768 + aoff);
#pragma unroll
            for (int np = 0; np < 4; np++) {
                uint32_t bH[4], bL[4];
                uint32_t boff = (ks>>2)*8192 +
                    SW128((uint32_t)((np*16 + (lane&7) + (lane>>4)*8)*128
                                     + (ks&3)*32 + ((lane>>3)&1)*16));
                ldsm4(bH, kh + boff);
                ldsm4(bL, kl + boff);
                mma16816(s[2*np],   aH, &bH[0]);
                mma16816(s[2*np+1], aH, &bH[2]);
                mma16816(s[2*np],   aH, &bL[0]);
                mma16816(s[2*np+1], aH, &bL[2]);
                mma16816(s[2*np],   aL, &bH[0]);
                mma16816(s[2*np+1], aL, &bH[2]);
            }
        }

        if (!allones) {
#pragma unroll
            for (int nt = 0; nt < 8; nt++)
#pragma unroll
                for (int e = 0; e < 4; e++) {
                    int qr = q0 + warp*16 + g + ((e>>1)<<3);
                    int kc = j0 + nt*8 + tg*2 + (e&1);
                    if (mask[((size_t)b*SEQ + qr)*SEQ + kc] == 0) s[nt][e] = -1e30f;
                }
        }

        // ---- online softmax (rows g, g+8; quad lanes share a row) ----
        float rm0 = s[0][0], rm1 = s[0][2];
#pragma unroll
        for (int nt = 0; nt < 8; nt++) {
            rm0 = fmaxf(rm0, fmaxf(s[nt][0], s[nt][1]));
            rm1 = fmaxf(rm1, fmaxf(s[nt][2], s[nt][3]));
        }
        rm0 = fmaxf(rm0, __shfl_xor_sync(0xffffffffu, rm0, 1));
        rm0 = fmaxf(rm0, __shfl_xor_sync(0xffffffffu, rm0, 2));
        rm1 = fmaxf(rm1, __shfl_xor_sync(0xffffffffu, rm1, 1));
        rm1 = fmaxf(rm1, __shfl_xor_sync(0xffffffffu, rm1, 2));
        float mn0 = fmaxf(m0r, rm0), mn1 = fmaxf(m1r, rm1);
        float c0 = __expf(m0r - mn0), c1 = __expf(m1r - mn1);
        float rs0 = 0.f, rs1 = 0.f;
#pragma unroll
        for (int nt = 0; nt < 8; nt++) {
            s[nt][0] = __expf(s[nt][0] - mn0);
            s[nt][1] = __expf(s[nt][1] - mn0);
            s[nt][2] = __expf(s[nt][2] - mn1);
            s[nt][3] = __expf(s[nt][3] - mn1);
            rs0 += s[nt][0] + s[nt][1];
            rs1 += s[nt][2] + s[nt][3];
        }
        rs0 += __shfl_xor_sync(0xffffffffu, rs0, 1);
        rs0 += __shfl_xor_sync(0xffffffffu, rs0, 2);
        rs1 += __shfl_xor_sync(0xffffffffu, rs1, 1);
        rs1 += __shfl_xor_sync(0xffffffffu, rs1, 2);
        m0r = mn0; m1r = mn1;
        l0r = l0r*c0 + rs0;
        l1r = l1r*c1 + rs1;
#pragma unroll
        for (int nt = 0; nt < 16; nt++) {
            o[nt][0] *= c0; o[nt][1] *= c0;
            o[nt][2] *= c1; o[nt][3] *= c1;
        }

        // ---- P.V : O[16, 128] += P[16, 64] @ VT^T ----
        // A-fragment identity: for k-group kg, score tiles s[2kg] (k0-7) and
        // s[2kg+1] (k8-15) supply exactly the P A-fragment:
        //   a0 = (row g,   k0-7)  = pack(s[2kg][0],   s[2kg][1])
        //   a1 = (row g+8, k0-7)  = pack(s[2kg][2],   s[2kg][3])
        //   a2 = (row g,   k8-15) = pack(s[2kg+1][0], s[2kg+1][1])
        //   a3 = (row g+8, k8-15) = pack(s[2kg+1][2], s[2kg+1][3])
#pragma unroll
        for (int kg = 0; kg < 4; kg++) {
            uint32_t aPh[4], aPl[4];
#pragma unroll
            for (int half = 0; half < 2; half++) {
                const float* sp = s[2*kg + half];
                uint32_t h01 = pack_bf16(sp[0], sp[1]);
                uint32_t h23 = pack_bf16(sp[2], sp[3]);
                aPh[half*2 + 0] = h01;
                aPh[half*2 + 1] = h23;
                aPl[half*2 + 0] = pack_bf16(sp[0] - __uint_as_float(h01<<16),
                                            sp[1] - __uint_as_float(h01 & 0xffff0000u));
                aPl[half*2 + 1] = pack_bf16(sp[2] - __uint_as_float(h23<<16),
                                            sp[3] - __uint_as_float(h23 & 0xffff0000u));
            }
#pragma unroll
            for (int np = 0; np < 8; np++) {
                uint32_t bH[4], bL[4];
                uint32_t boff =
                    SW128((uint32_t)((np*16 + (lane&7) + (lane>>4)*8)*128
                                     + kg*32 + ((lane>>3)&1)*16));
                ldsm4(bH, vh + boff);
                ldsm4(bL, vl + boff);
                mma16816(o[2*np],   aPh, &bH[0]);
                mma16816(o[2*np+1], aPh, &bH[2]);
                mma16816(o[2*np],   aPh, &bL[0]);
                mma16816(o[2*np+1], aPh, &bL[2]);
                mma16816(o[2*np],   aPl, &bH[0]);
                mma16816(o[2*np+1], aPl, &bH[2]);
            }
        }
        __syncthreads();
    }

    // ---- epilogue: O/l -> bf16 hi/lo into g_Ahi/g_Alo ----
    float inv0 = 1.f / l0r, inv1 = 1.f / l1r;
    const size_t r0 = (size_t)(b*SEQ + q0 + warp*16 + g);
    const size_t r1 = r0 + 8;
#pragma unroll
    for (int nt = 0; nt < 16; nt++) {
        const int col = h*HD + nt*8 + tg*2;
        float v0 = o[nt][0]*inv0, v1 = o[nt][1]*inv0;
        float v2 = o[nt][2]*inv1, v3 = o[nt][3]*inv1;
        uint32_t h01 = pack_bf16(v0, v1);
        uint32_t h23 = pack_bf16(v2, v3);
        uint32_t l01 = pack_bf16(v0 - __uint_as_float(h01<<16),
                                 v1 - __uint_as_float(h01 & 0xffff0000u));
        uint32_t l23 = pack_bf16(v2 - __uint_as_float(h23<<16),
                                 v3 - __uint_as_float(h23 & 0xffff0000u));
        *(uint32_t*)&g_Ahi[r0*HID + col] = h01;
        *(uint32_t*)&g_Ahi[r1*HID + col] = h23;
        *(uint32_t*)&g_Alo[r0*HID + col] = l01;
        *(uint32_t*)&g_Alo[r1*HID + col] = l23;
    }
}

// ---------------- launch ----------------
extern "C" void kernel_launch(void* const* d_in, const int* in_sizes, int n_in,
                              void* d_out, int out_size)
{
    const float* X  = (const float*)d_in[0];
    const int* mask = (const int*)  d_in[1];
    const float* Wq = (const float*)d_in[2];
    const float* bq = (const float*)d_in[3];
    const float* Wk = (const float*)d_in[4];
    const float* bk = (const float*)d_in[5];
    const float* Wv = (const float*)d_in[6];
    const float* bv = (const float*)d_in[7];
    const float* Wo = (const float*)d_in[8];
    const float* bo = (const float*)d_in[9];
    float* out = (float*)d_out;

    float *kp, *vp;
    cudaGetSymbolAddress((void**)&kp, g_K);
    cudaGetSymbolAddress((void**)&vp, g_V);

    __nv_bfloat16 *xh, *xl, *qh, *ql, *ah, *al, *kh, *kl, *vth, *vtl;
    __nv_bfloat16 *wqh, *wql, *woh, *wol, *wkh, *wkl, *wvh, *wvl;
    cudaGetSymbolAddress((void**)&xh,  g_Xhi);  cudaGetSymbolAddress((void**)&xl,  g_Xlo);
    cudaGetSymbolAddress((void**)&qh,  g_Qhi);  cudaGetSymbolAddress((void**)&ql,  g_Qlo);
    cudaGetSymbolAddress((void**)&ah,  g_Ahi);  cudaGetSymbolAddress((void**)&al,  g_Alo);
    cudaGetSymbolAddress((void**)&kh,  g_Khi);  cudaGetSymbolAddress((void**)&kl,  g_Klo);
    cudaGetSymbolAddress((void**)&vth, g_VTh);  cudaGetSymbolAddress((void**)&vtl, g_VTl);
    cudaGetSymbolAddress((void**)&wqh, g_WqTh); cudaGetSymbolAddress((void**)&wql, g_WqTl);
    cudaGetSymbolAddress((void**)&woh, g_WoTh); cudaGetSymbolAddress((void**)&wol, g_WoTl);
    cudaGetSymbolAddress((void**)&wkh, g_WkTh); cudaGetSymbolAddress((void**)&wkl, g_WkTl);
    cudaGetSymbolAddress((void**)&wvh, g_WvTh); cudaGetSymbolAddress((void**)&wvl, g_WvTl);

    cudaFuncSetAttribute(gemm_mma_kernel<false>,
                         cudaFuncAttributeMaxDynamicSharedMemorySize, GEMM_DYN);
    cudaFuncSetAttribute(gemm_mma_kernel<true>,
                         cudaFuncAttributeMaxDynamicSharedMemorySize, GEMM_DYN);
    cudaFuncSetAttribute(attn_mma_kernel,
                         cudaFuncAttributeMaxDynamicSharedMemorySize, ATTN_DYN);

    flag_init_kernel<<<1, 1>>>();
    mask_scan_kernel<<<512, 256>>>(mask);

    split_kernel<<<4096, 256>>>(X, xh, xl, MTOT*HID/4);
    tsplit_kernel<<<dim3(HID/32, HID/32), dim3(32,8)>>>(Wq, wqh, wql, HID, HID);
    tsplit_kernel<<<dim3(HD/32,  HID/32), dim3(32,8)>>>(Wk, wkh, wkl, HID, HD);
    tsplit_kernel<<<dim3(HD/32,  HID/32), dim3(32,8)>>>(Wv, wvh, wvl, HID, HD);
    tsplit_kernel<<<dim3(HID/32, HID/32), dim3(32,8)>>>(Wo, woh, wol, HID, HID);

    const float scale = 0.088388347648318447f;  // 1/sqrt(128)
    gemm_mma_kernel<true><<<dim3(HID/128, MTOT/128), 256, GEMM_DYN>>>(
        xh, xl, wqh, wql, bq, nullptr, qh, ql, scale, MTOT, HID, HID);
    gemm_mma_kernel<false><<<dim3(1, MTOT/128), 256, GEMM_DYN>>>(
        xh, xl, wkh, wkl, bk, kp, nullptr, nullptr, 1.f, MTOT, HD, HID);
    gemm_mma_kernel<false><<<dim3(1, MTOT/128), 256, GEMM_DYN>>>(
        xh, xl, wvh, wvl, bv, vp, nullptr, nullptr, 1.f, MTOT, HD, HID);

    split_kernel<<<512, 256>>>(kp, kh, kl, MTOT*HD/4);
    vtsplit_kernel<<<dim3(SEQ/32, HD/32, BATCH), dim3(32,8)>>>(vp, vth, vtl);

    attn_mma_kernel<<<dim3(SEQ/128, NH, BATCH), 256, ATTN_DYN>>>(mask);

    gemm_mma_kernel<false><<<dim3(HID/128, MTOT/128), 256, GEMM_DYN>>>(
        ah, al, woh, wol, bo, out, nullptr, nullptr, 1.f, MTOT, HID, HID);
}

// round 6
// speedup vs baseline: 7.6565x; 1.4594x over previous
#include <cuda_runtime.h>
#include <cuda_fp16.h>
#include <cstdint>
#include <math.h>

#define BATCH 2
#define SEQ   2048
#define HID   2048
#define NH    16
#define HD    128
#define MTOT  (BATCH*SEQ)

// ---------------- mma GEMM config (2-term fp16: A single, B hi/lo) ----------------
#define CHUNK_BYTES 49152           // 3 tiles x 128rows x 128B (A, Bhi, Blo)
#define GEMM_DYN    (2*CHUNK_BYTES + 1024)

// ---------------- mma attention config ----------------
#define BKV 64
#define ATTN_DYN (32768 + 2*65536 + 1024)  // Q(32KB) + 2 KV bufs(64KB each)

// ---------------- device scratch ----------------
__device__ float g_KV[(size_t)MTOT*256];    // fused K|V projection out (fp32)
__device__ int   g_allones;

__device__ __half g_Xh [(size_t)MTOT*HID];
__device__ __half g_Qh [(size_t)MTOT*HID];
__device__ __half g_Ah [(size_t)MTOT*HID];
__device__ __half g_Khi[(size_t)MTOT*HD];
__device__ __half g_Klo[(size_t)MTOT*HD];
__device__ __half g_VTh[(size_t)BATCH*HD*SEQ];
__device__ __half g_VTl[(size_t)BATCH*HD*SEQ];
__device__ __half g_WqTh[(size_t)HID*HID];
__device__ __half g_WqTl[(size_t)HID*HID];
__device__ __half g_WoTh[(size_t)HID*HID];
__device__ __half g_WoTl[(size_t)HID*HID];
__device__ __half g_WkvTh[(size_t)256*HID];  // rows 0-127: WkT, 128-255: WvT
__device__ __half g_WkvTl[(size_t)256*HID];
__device__ float  g_bkv[256];

// ---------------- helpers ----------------
__device__ __forceinline__ uint32_t smem_u32(const void* p) {
    uint32_t a;
    asm("{ .reg .u64 t; cvta.to.shared.u64 t, %1; cvt.u32.u64 %0, t; }" : "=r"(a) : "l"(p));
    return a;
}
__device__ __forceinline__ void cp16(uint32_t dst, const void* src) {
    asm volatile("cp.async.cg.shared.global [%0], [%1], 16;" :: "r"(dst), "l"(src));
}
__device__ __forceinline__ void ldsm4(uint32_t* r, uint32_t addr) {
    asm volatile("ldmatrix.sync.aligned.m8n8.x4.shared.b16 {%0,%1,%2,%3}, [%4];"
                 : "=r"(r[0]), "=r"(r[1]), "=r"(r[2]), "=r"(r[3]) : "r"(addr));
}
__device__ __forceinline__ void mma16816(float* c, const uint32_t* a, const uint32_t* b) {
    asm volatile(
        "mma.sync.aligned.m16n8k16.row.col.f32.f16.f16.f32 "
        "{%0,%1,%2,%3}, {%4,%5,%6,%7}, {%8,%9}, {%0,%1,%2,%3};"
        : "+f"(c[0]), "+f"(c[1]), "+f"(c[2]), "+f"(c[3])
        : "r"(a[0]), "r"(a[1]), "r"(a[2]), "r"(a[3]), "r"(b[0]), "r"(b[1]));
}
// packed f16x2: lo in lower half, hi in upper half
__device__ __forceinline__ uint32_t pack_f16(float lo, float hi) {
    uint32_t r;
    asm("cvt.rn.f16x2.f32 %0, %1, %2;" : "=r"(r) : "f"(hi), "f"(lo));
    return r;
}
#define SW128(x) ((x) ^ (((x) >> 3) & 0x70))

// ---------------- mask pre-scan ----------------
__global__ void flag_init_kernel() { g_allones = 1; }

__global__ void mask_scan_kernel(const int* __restrict__ mask) {
    const int4* m4 = (const int4*)mask;
    const int total = BATCH*SEQ*SEQ/4;
    int bad = 0;
    for (int i = blockIdx.x*blockDim.x + threadIdx.x; i < total;
         i += gridDim.x*blockDim.x) {
        int4 v = m4[i];
        if ((v.x == 0) | (v.y == 0) | (v.z == 0) | (v.w == 0)) bad = 1;
    }
    if (bad) g_allones = 0;
}

// ---------------- fp32 -> fp16 (single) ----------------
__global__ void xhalf_kernel(const float* __restrict__ x,
                             __half* __restrict__ o, int n4) {
    __half2* o2 = (__half2*)o;
    for (int i = blockIdx.x*blockDim.x + threadIdx.x; i < n4;
         i += gridDim.x*blockDim.x) {
        float4 v = ((const float4*)x)[i];
        o2[i*2+0] = __floats2half2_rn(v.x, v.y);
        o2[i*2+1] = __floats2half2_rn(v.z, v.w);
    }
}

// ---------------- W[K,N] -> WT[N,K] fp16 hi/lo transpose-split ----------------
__global__ void tsplit_kernel(const float* __restrict__ W,
                              __half* __restrict__ Th,
                              __half* __restrict__ Tl, int K, int N) {
    __shared__ float t[32][33];
    int x = blockIdx.x*32 + threadIdx.x;
#pragma unroll
    for (int j = 0; j < 4; j++) {
        int y = blockIdx.y*32 + threadIdx.y + j*8;
        t[threadIdx.y + j*8][threadIdx.x] = W[(size_t)y*N + x];
    }
    __syncthreads();
    int xo = blockIdx.y*32 + threadIdx.x;
#pragma unroll
    for (int j = 0; j < 4; j++) {
        int yo = blockIdx.x*32 + threadIdx.y + j*8;
        float v = t[threadIdx.x][threadIdx.y + j*8];
        __half h = __float2half_rn(v);
        Th[(size_t)yo*K + xo] = h;
        Tl[(size_t)yo*K + xo] = __float2half_rn(v - __half2float(h));
    }
}

// ---------------- bias concat bk||bv ----------------
__global__ void bkv_kernel(const float* __restrict__ bk, const float* __restrict__ bv) {
    int i = threadIdx.x;
    g_bkv[i] = (i < 128) ? bk[i] : bv[i-128];
}

// ---------------- K half-split from fused KV (cols 0-127) ----------------
__global__ void ksplit_kernel() {
    int i = blockIdx.x*blockDim.x + threadIdx.x;   // over MTOT*32 float4 units
    int r  = i >> 5;
    int c4 = i & 31;
    float4 v = *(const float4*)&g_KV[(size_t)r*256 + c4*4];
    __half h0 = __float2half_rn(v.x), h1 = __float2half_rn(v.y);
    __half h2 = __float2half_rn(v.z), h3 = __float2half_rn(v.w);
    __half2* kh = (__half2*)g_Khi;
    __half2* kl = (__half2*)g_Klo;
    kh[r*64 + c4*2 + 0] = __half2(h0, h1);
    kh[r*64 + c4*2 + 1] = __half2(h2, h3);
    kl[r*64 + c4*2 + 0] = __half2(__float2half_rn(v.x - __half2float(h0)),
                                  __float2half_rn(v.y - __half2float(h1)));
    kl[r*64 + c4*2 + 1] = __half2(__float2half_rn(v.z - __half2float(h2)),
                                  __float2half_rn(v.w - __half2float(h3)));
}

// ---------------- V (cols 128-255 of KV) -> VT[b][d][s] fp16 hi/lo ----------------
__global__ void vtsplit_kernel() {
    __shared__ float t[32][33];
    int b  = blockIdx.z;
    int s0 = blockIdx.x*32;
    int d0 = blockIdx.y*32;
#pragma unroll
    for (int j = 0; j < 4; j++) {
        int s = s0 + threadIdx.y + j*8;
        t[threadIdx.y + j*8][threadIdx.x] =
            g_KV[((size_t)b*SEQ + s)*256 + 128 + d0 + threadIdx.x];
    }
    __syncthreads();
#pragma unroll
    for (int j = 0; j < 4; j++) {
        int d = d0 + threadIdx.y + j*8;
        float v = t[threadIdx.x][threadIdx.y + j*8];
        __half h = __float2half_rn(v);
        size_t o = ((size_t)b*HD + d)*SEQ + s0 + threadIdx.x;
        g_VTh[o] = h;
        g_VTl[o] = __float2half_rn(v - __half2float(h));
    }
}

// ---------------- mma.sync fp16 2-term GEMM ----------------
// C[M,N] = A@Bhi^T + A@Blo^T + bias ; A[M,K] f16, B[N,K] f16 hi/lo, K-major.
// OUTF16: write ((acc+bias)*oscale) as f16 instead of fp32.
template<bool OUTF16>
__global__ __launch_bounds__(256) void gemm_mma_kernel(
    const __half* __restrict__ A,
    const __half* __restrict__ Bhi, const __half* __restrict__ Blo,
    const float* __restrict__ bias, float* __restrict__ C,
    __half* __restrict__ Cf, float oscale, int M, int N, int K)
{
    extern __shared__ char dyn[];
    const int tid  = threadIdx.x;
    const int warp = tid >> 5;
    const int lane = tid & 31;
    const int wm   = warp >> 2;
    const int wn   = warp & 3;
    const int n0 = blockIdx.x * 128;
    const int m0 = blockIdx.y * 128;

    const uint32_t sbase = (smem_u32(dyn) + 1023u) & ~1023u;

    float acc[4][4][4];
#pragma unroll
    for (int mt = 0; mt < 4; mt++)
#pragma unroll
        for (int nt = 0; nt < 4; nt++)
#pragma unroll
            for (int q = 0; q < 4; q++) acc[mt][nt][q] = 0.f;

    auto stage = [&](uint32_t tb, int k0) {
#pragma unroll
        for (int u = tid; u < 3072; u += 256) {
            int t   = u >> 10;
            int idx = u & 1023;
            int row = idx >> 3;
            int c16 = idx & 7;
            const __half* src;
            if (t == 0)      src = A   + (size_t)(m0+row)*K + k0 + c16*8;
            else if (t == 1) src = Bhi + (size_t)(n0+row)*K + k0 + c16*8;
            else             src = Blo + (size_t)(n0+row)*K + k0 + c16*8;
            cp16(tb + t*16384 + SW128((uint32_t)(row*128 + c16*16)), src);
        }
        asm volatile("cp.async.commit_group;" ::: "memory");
    };

    const int nch = K / 64;
    stage(sbase, 0);

    for (int ch = 0; ch < nch; ch++) {
        if (ch + 1 < nch) {
            stage(sbase + ((ch+1)&1)*CHUNK_BYTES, (ch+1)*64);
            asm volatile("cp.async.wait_group 1;" ::: "memory");
        } else {
            asm volatile("cp.async.wait_group 0;" ::: "memory");
        }
        __syncthreads();

        const uint32_t tb  = sbase + (ch&1)*CHUNK_BYTES;
        const uint32_t tA = tb, tBh = tb + 16384, tBl = tb + 32768;

#pragma unroll
        for (int ks = 0; ks < 4; ks++) {
            uint32_t ah[4][4], bh[2][4], bl[2][4];
            const uint32_t abyte = (uint32_t)(ks*32 + (lane>>4)*16);
            const int      arow  = wm*64 + (lane & 15);
#pragma unroll
            for (int mt = 0; mt < 4; mt++) {
                uint32_t off = SW128((uint32_t)((arow + mt*16)*128) + abyte);
                ldsm4(ah[mt], tA + off);
            }
            const uint32_t bbyte = (uint32_t)(ks*32 + ((lane>>3)&1)*16);
            const int      brow  = wn*32 + (lane & 7) + (lane>>4)*8;
#pragma unroll
            for (int np = 0; np < 2; np++) {
                uint32_t off = SW128((uint32_t)((brow + np*16)*128) + bbyte);
                ldsm4(bh[np], tBh + off);
                ldsm4(bl[np], tBl + off);
            }
#pragma unroll
            for (int mt = 0; mt < 4; mt++)
#pragma unroll
                for (int nt = 0; nt < 4; nt++) {
                    const uint32_t* bph = &bh[nt>>1][(nt&1)*2];
                    const uint32_t* bpl = &bl[nt>>1][(nt&1)*2];
                    mma16816(acc[mt][nt], ah[mt], bph);
                    mma16816(acc[mt][nt], ah[mt], bpl);
                }
        }
        __syncthreads();
    }

    const int g  = lane >> 2;
    const int tg = lane & 3;
#pragma unroll
    for (int mt = 0; mt < 4; mt++) {
        const int r0 = m0 + wm*64 + mt*16 + g;
#pragma unroll
        for (int nt = 0; nt < 4; nt++) {
            const int col = n0 + wn*32 + nt*8 + tg*2;
            const float b0 = bias[col], b1 = bias[col+1];
            if (OUTF16) {
                float v0 = (acc[mt][nt][0] + b0)*oscale;
                float v1 = (acc[mt][nt][1] + b1)*oscale;
                float v2 = (acc[mt][nt][2] + b0)*oscale;
                float v3 = (acc[mt][nt][3] + b1)*oscale;
                *(uint32_t*)&Cf[(size_t)r0*N + col]     = pack_f16(v0, v1);
                *(uint32_t*)&Cf[(size_t)(r0+8)*N + col] = pack_f16(v2, v3);
            } else {
                float2 v0 = make_float2(acc[mt][nt][0] + b0, acc[mt][nt][1] + b1);
                float2 v1 = make_float2(acc[mt][nt][2] + b0, acc[mt][nt][3] + b1);
                *(float2*)&C[(size_t)r0*N + col]     = v0;
                *(float2*)&C[(size_t)(r0+8)*N + col] = v1;
            }
        }
    }
}

// ---------------- mma.sync flash attention (fp16, 2-term) ----------------
// grid (SEQ/128, NH, BATCH), 256 threads (8 warps x 16 q-rows).
// QK^T: A=Q[16,128] f16 single, B=K[64,128] f16 hi/lo (2-term).
// P.V : A=P f16 single (from score C-fragments), B=VT[128,64] f16 hi/lo (2-term).
__global__ __launch_bounds__(256) void attn_mma_kernel(const int* __restrict__ mask)
{
    extern __shared__ char dyn[];
    const int tid  = threadIdx.x;
    const int warp = tid >> 5;
    const int lane = tid & 31;
    const int g    = lane >> 2;
    const int tg   = lane & 3;
    const int h  = blockIdx.y;
    const int b  = blockIdx.z;
    const int q0 = blockIdx.x * 128;
    const int allones = g_allones;

    const uint32_t base = (smem_u32(dyn) + 1023u) & ~1023u;
    const uint32_t sQ   = base;                 // Q f16: chunk0@0, chunk1@16384
    const uint32_t sKV0 = base + 32768;         // per buf: Kh(16KB), Kl, Vh, Vl

    // ---- stage Q (once) ----
    for (int u = tid; u < 2048; u += 256) {
        int chunk = u >> 10, r = (u >> 3) & 127, c16 = u & 7;
        const __half* src =
            g_Qh + ((size_t)(b*SEQ + q0 + r))*HID + h*HD + chunk*64 + c16*8;
        cp16(sQ + chunk*16384 + SW128((uint32_t)(r*128 + c16*16)), src);
    }

    auto stageKV = [&](uint32_t bb, int j0) {
#pragma unroll
        for (int u = tid; u < 2048; u += 256) {   // K hi/lo
            int t = u >> 10, idx = u & 1023;
            int chunk = idx >> 9, r = (idx >> 3) & 63, c16 = idx & 7;
            const __half* src =
                (t ? g_Klo : g_Khi) + ((size_t)(b*SEQ + j0 + r))*HD + chunk*64 + c16*8;
            cp16(bb + t*16384 + chunk*8192 + SW128((uint32_t)(r*128 + c16*16)), src);
        }
#pragma unroll
        for (int u = tid; u < 2048; u += 256) {   // VT hi/lo
            int t = u >> 10, idx = u & 1023;
            int r = idx >> 3, c16 = idx & 7;
            const __half* src =
                (t ? g_VTl : g_VTh) + ((size_t)b*HD + r)*SEQ + j0 + c16*8;
            cp16(bb + 32768 + t*16384 + SW128((uint32_t)(r*128 + c16*16)), src);
        }
        asm volatile("cp.async.commit_group;" ::: "memory");
    };

    stageKV(sKV0, 0);

    float m0r = -1e30f, m1r = -1e30f, l0r = 0.f, l1r = 0.f;
    float o[16][4];
#pragma unroll
    for (int nt = 0; nt < 16; nt++)
#pragma unroll
        for (int e = 0; e < 4; e++) o[nt][e] = 0.f;

    const int NT = SEQ / BKV;
    for (int t = 0; t < NT; t++) {
        if (t + 1 < NT) {
            stageKV(sKV0 + ((t+1)&1)*65536, (t+1)*BKV);
            asm volatile("cp.async.wait_group 1;" ::: "memory");
        } else {
            asm volatile("cp.async.wait_group 0;" ::: "memory");
        }
        __syncthreads();

        const uint32_t bb = sKV0 + (t&1)*65536;
        const uint32_t kh = bb, kl = bb + 16384, vh = bb + 32768, vl = bb + 49152;
        const int j0 = t * BKV;

        // ---- scores S[16, 64] = Q @ (Kh + Kl)^T ----
        float s[8][4];
#pragma unroll
        for (int nt = 0; nt < 8; nt++)
#pragma unroll
            for (int e = 0; e < 4; e++) s[nt][e] = 0.f;

#pragma unroll
        for (int ks = 0; ks < 8; ks++) {
            uint32_t aH[4];
            uint32_t aoff = (ks>>2)*16384 +
                SW128((uint32_t)((warp*16 + (lane & 15))*128 + (ks&3)*32 + (lane>>4)*16));
            ldsm4(aH, sQ + aoff);
#pragma unroll
            for (int np = 0; np < 4; np++) {
                uint32_t bH[4], bL[4];
                uint32_t boff = (ks>>2)*8192 +
                    SW128((uint32_t)((np*16 + (lane&7) + (lane>>4)*8)*128
                                     + (ks&3)*32 + ((lane>>3)&1)*16));
                ldsm4(bH, kh + boff);
                ldsm4(bL, kl + boff);
                mma16816(s[2*np],   aH, &bH[0]);
                mma16816(s[2*np+1], aH, &bH[2]);
                mma16816(s[2*np],   aH, &bL[0]);
                mma16816(s[2*np+1], aH, &bL[2]);
            }
        }

        if (!allones) {
#pragma unroll
            for (int nt = 0; nt < 8; nt++)
#pragma unroll
                for (int e = 0; e < 4; e++) {
                    int qr = q0 + warp*16 + g + ((e>>1)<<3);
                    int kc = j0 + nt*8 + tg*2 + (e&1);
                    if (mask[((size_t)b*SEQ + qr)*SEQ + kc] == 0) s[nt][e] = -1e30f;
                }
        }

        // ---- online softmax (rows g, g+8; quad lanes share a row) ----
        float rm0 = s[0][0], rm1 = s[0][2];
#pragma unroll
        for (int nt = 0; nt < 8; nt++) {
            rm0 = fmaxf(rm0, fmaxf(s[nt][0], s[nt][1]));
            rm1 = fmaxf(rm1, fmaxf(s[nt][2], s[nt][3]));
        }
        rm0 = fmaxf(rm0, __shfl_xor_sync(0xffffffffu, rm0, 1));
        rm0 = fmaxf(rm0, __shfl_xor_sync(0xffffffffu, rm0, 2));
        rm1 = fmaxf(rm1, __shfl_xor_sync(0xffffffffu, rm1, 1));
        rm1 = fmaxf(rm1, __shfl_xor_sync(0xffffffffu, rm1, 2));
        float mn0 = fmaxf(m0r, rm0), mn1 = fmaxf(m1r, rm1);
        float c0 = __expf(m0r - mn0), c1 = __expf(m1r - mn1);
        float rs0 = 0.f, rs1 = 0.f;
#pragma unroll
        for (int nt = 0; nt < 8; nt++) {
            s[nt][0] = __expf(s[nt][0] - mn0);
            s[nt][1] = __expf(s[nt][1] - mn0);
            s[nt][2] = __expf(s[nt][2] - mn1);
            s[nt][3] = __expf(s[nt][3] - mn1);
            rs0 += s[nt][0] + s[nt][1];
            rs1 += s[nt][2] + s[nt][3];
        }
        rs0 += __shfl_xor_sync(0xffffffffu, rs0, 1);
        rs0 += __shfl_xor_sync(0xffffffffu, rs0, 2);
        rs1 += __shfl_xor_sync(0xffffffffu, rs1, 1);
        rs1 += __shfl_xor_sync(0xffffffffu, rs1, 2);
        m0r = mn0; m1r = mn1;
        l0r = l0r*c0 + rs0;
        l1r = l1r*c1 + rs1;
#pragma unroll
        for (int nt = 0; nt < 16; nt++) {
            o[nt][0] *= c0; o[nt][1] *= c0;
            o[nt][2] *= c1; o[nt][3] *= c1;
        }

        // ---- P.V : O[16, 128] += P[16, 64] @ (Vh + Vl)^T ----
        // A-fragment identity: k-group kg uses score tiles s[2kg] (k0-7) and
        // s[2kg+1] (k8-15):
        //   a0 = (row g,   k0-7)  = pack(s[2kg][0],   s[2kg][1])
        //   a1 = (row g+8, k0-7)  = pack(s[2kg][2],   s[2kg][3])
        //   a2 = (row g,   k8-15) = pack(s[2kg+1][0], s[2kg+1][1])
        //   a3 = (row g+8, k8-15) = pack(s[2kg+1][2], s[2kg+1][3])
#pragma unroll
        for (int kg = 0; kg < 4; kg++) {
            uint32_t aP[4];
            aP[0] = pack_f16(s[2*kg][0],   s[2*kg][1]);
            aP[1] = pack_f16(s[2*kg][2],   s[2*kg][3]);
            aP[2] = pack_f16(s[2*kg+1][0], s[2*kg+1][1]);
            aP[3] = pack_f16(s[2*kg+1][2], s[2*kg+1][3]);
#pragma unroll
            for (int np = 0; np < 8; np++) {
                uint32_t bH[4], bL[4];
                uint32_t boff =
                    SW128((uint32_t)((np*16 + (lane&7) + (lane>>4)*8)*128
                                     + kg*32 + ((lane>>3)&1)*16));
                ldsm4(bH, vh + boff);
                ldsm4(bL, vl + boff);
                mma16816(o[2*np],   aP, &bH[0]);
                mma16816(o[2*np+1], aP, &bH[2]);
                mma16816(o[2*np],   aP, &bL[0]);
                mma16816(o[2*np+1], aP, &bL[2]);
            }
        }
        __syncthreads();
    }

    // ---- epilogue: O/l -> f16 into g_Ah ----
    float inv0 = 1.f / l0r, inv1 = 1.f / l1r;
    const size_t r0 = (size_t)(b*SEQ + q0 + warp*16 + g);
    const size_t r1 = r0 + 8;
#pragma unroll
    for (int nt = 0; nt < 16; nt++) {
        const int col = h*HD + nt*8 + tg*2;
        *(uint32_t*)&g_Ah[r0*HID + col] = pack_f16(o[nt][0]*inv0, o[nt][1]*inv0);
        *(uint32_t*)&g_Ah[r1*HID + col] = pack_f16(o[nt][2]*inv1, o[nt][3]*inv1);
    }
}

// ---------------- launch ----------------
extern "C" void kernel_launch(void* const* d_in, const int* in_sizes, int n_in,
                              void* d_out, int out_size)
{
    const float* X  = (const float*)d_in[0];
    const int* mask = (const int*)  d_in[1];
    const float* Wq = (const float*)d_in[2];
    const float* bq = (const float*)d_in[3];
    const float* Wk = (const float*)d_in[4];
    const float* bk = (const float*)d_in[5];
    const float* Wv = (const float*)d_in[6];
    const float* bv = (const float*)d_in[7];
    const float* Wo = (const float*)d_in[8];
    const float* bo = (const float*)d_in[9];
    float* out = (float*)d_out;

    float* kvp;
    cudaGetSymbolAddress((void**)&kvp, g_KV);
    float* bkvp;
    cudaGetSymbolAddress((void**)&bkvp, g_bkv);

    __half *xh, *qh, *ah, *wqh, *wql, *woh, *wol, *wkvh, *wkvl;
    cudaGetSymbolAddress((void**)&xh,   g_Xh);
    cudaGetSymbolAddress((void**)&qh,   g_Qh);
    cudaGetSymbolAddress((void**)&ah,   g_Ah);
    cudaGetSymbolAddress((void**)&wqh,  g_WqTh);  cudaGetSymbolAddress((void**)&wql,  g_WqTl);
    cudaGetSymbolAddress((void**)&woh,  g_WoTh);  cudaGetSymbolAddress((void**)&wol,  g_WoTl);
    cudaGetSymbolAddress((void**)&wkvh, g_WkvTh); cudaGetSymbolAddress((void**)&wkvl, g_WkvTl);

    cudaFuncSetAttribute(gemm_mma_kernel<false>,
                         cudaFuncAttributeMaxDynamicSharedMemorySize, GEMM_DYN);
    cudaFuncSetAttribute(gemm_mma_kernel<true>,
                         cudaFuncAttributeMaxDynamicSharedMemorySize, GEMM_DYN);
    cudaFuncSetAttribute(attn_mma_kernel,
                         cudaFuncAttributeMaxDynamicSharedMemorySize, ATTN_DYN);

    flag_init_kernel<<<1, 1>>>();
    mask_scan_kernel<<<512, 256>>>(mask);

    xhalf_kernel<<<4096, 256>>>(X, xh, MTOT*HID/4);
    tsplit_kernel<<<dim3(HID/32, HID/32), dim3(32,8)>>>(Wq, wqh, wql, HID, HID);
    tsplit_kernel<<<dim3(HD/32,  HID/32), dim3(32,8)>>>(Wk, wkvh, wkvl, HID, HD);
    tsplit_kernel<<<dim3(HD/32,  HID/32), dim3(32,8)>>>(
        Wv, wkvh + (size_t)128*HID, wkvl + (size_t)128*HID, HID, HD);
    tsplit_kernel<<<dim3(HID/32, HID/32), dim3(32,8)>>>(Wo, woh, wol, HID, HID);
    bkv_kernel<<<1, 256>>>(bk, bv);

    const float scale = 0.088388347648318447f;  // 1/sqrt(128)
    gemm_mma_kernel<true><<<dim3(HID/128, MTOT/128), 256, GEMM_DYN>>>(
        xh, wqh, wql, bq, nullptr, qh, scale, MTOT, HID, HID);
    gemm_mma_kernel<false><<<dim3(2, MTOT/128), 256, GEMM_DYN>>>(
        xh, wkvh, wkvl, bkvp, kvp, nullptr, 1.f, MTOT, 256, HID);

    ksplit_kernel<<<MTOT*32/256, 256>>>();
    vtsplit_kernel<<<dim3(SEQ/32, HD/32, BATCH), dim3(32,8)>>>();

    attn_mma_kernel<<<dim3(SEQ/128, NH, BATCH), 256, ATTN_DYN>>>(mask);

    gemm_mma_kernel<false><<<dim3(HID/128, MTOT/128), 256, GEMM_DYN>>>(
        ah, woh, wol, bo, out, nullptr, 1.f, MTOT, HID, HID);
}

// round 7
// speedup vs baseline: 13.9210x; 1.8182x over previous
#include <cuda_runtime.h>
#include <cuda_fp16.h>
#include <cstdint>
#include <math.h>

#define BATCH 2
#define SEQ   2048
#define HID   2048
#define NH    16
#define HD    128
#define MTOT  (BATCH*SEQ)
#define NQKV  2304   // 2048 (Q) + 128 (K) + 128 (V)

// ---------------- mma GEMM config (single f16, A + B) ----------------
#define CHUNK_BYTES 32768           // 2 tiles x 128rows x 128B (A, B)
#define GEMM_DYN    (2*CHUNK_BYTES + 1024)

// ---------------- mma attention config ----------------
#define BKV 64
#define ATTN_DYN (32768 + 2*32768 + 1024)  // Q(32KB) + 2 KV bufs(32KB each)

// ---------------- device scratch ----------------
__device__ float  g_V[(size_t)MTOT*HD];     // V projection (fp32, pre-transpose)
__device__ int    g_allones;

__device__ __half g_Xh [(size_t)MTOT*HID];
__device__ __half g_Qh [(size_t)MTOT*HID];
__device__ __half g_Ah [(size_t)MTOT*HID];
__device__ __half g_Kh [(size_t)MTOT*HD];
__device__ __half g_VTh[(size_t)BATCH*HD*SEQ];
__device__ __half g_WT [(size_t)NQKV*HID];  // rows: WqT(0-2047) WkT(2048-2175) WvT(2176-2303)
__device__ __half g_WoT[(size_t)HID*HID];
__device__ float  g_bqkv[NQKV];

// ---------------- helpers ----------------
__device__ __forceinline__ uint32_t smem_u32(const void* p) {
    uint32_t a;
    asm("{ .reg .u64 t; cvta.to.shared.u64 t, %1; cvt.u32.u64 %0, t; }" : "=r"(a) : "l"(p));
    return a;
}
__device__ __forceinline__ void cp16(uint32_t dst, const void* src) {
    asm volatile("cp.async.cg.shared.global [%0], [%1], 16;" :: "r"(dst), "l"(src));
}
__device__ __forceinline__ void ldsm4(uint32_t* r, uint32_t addr) {
    asm volatile("ldmatrix.sync.aligned.m8n8.x4.shared.b16 {%0,%1,%2,%3}, [%4];"
                 : "=r"(r[0]), "=r"(r[1]), "=r"(r[2]), "=r"(r[3]) : "r"(addr));
}
__device__ __forceinline__ void mma16816(float* c, const uint32_t* a, const uint32_t* b) {
    asm volatile(
        "mma.sync.aligned.m16n8k16.row.col.f32.f16.f16.f32 "
        "{%0,%1,%2,%3}, {%4,%5,%6,%7}, {%8,%9}, {%0,%1,%2,%3};"
        : "+f"(c[0]), "+f"(c[1]), "+f"(c[2]), "+f"(c[3])
        : "r"(a[0]), "r"(a[1]), "r"(a[2]), "r"(a[3]), "r"(b[0]), "r"(b[1]));
}
// packed f16x2: lo in lower half, hi in upper half
__device__ __forceinline__ uint32_t pack_f16(float lo, float hi) {
    uint32_t r;
    asm("cvt.rn.f16x2.f32 %0, %1, %2;" : "=r"(r) : "f"(hi), "f"(lo));
    return r;
}
#define SW128(x) ((x) ^ (((x) >> 3) & 0x70))

// ---------------- mask pre-scan ----------------
__global__ void flag_init_kernel() { g_allones = 1; }

__global__ void mask_scan_kernel(const int* __restrict__ mask) {
    const int4* m4 = (const int4*)mask;
    const int total = BATCH*SEQ*SEQ/4;
    int bad = 0;
    for (int i = blockIdx.x*blockDim.x + threadIdx.x; i < total;
         i += gridDim.x*blockDim.x) {
        int4 v = m4[i];
        if ((v.x == 0) | (v.y == 0) | (v.z == 0) | (v.w == 0)) bad = 1;
    }
    if (bad) g_allones = 0;
}

// ---------------- fp32 -> fp16 ----------------
__global__ void xhalf_kernel(const float* __restrict__ x,
                             __half* __restrict__ o, int n4) {
    __half2* o2 = (__half2*)o;
    for (int i = blockIdx.x*blockDim.x + threadIdx.x; i < n4;
         i += gridDim.x*blockDim.x) {
        float4 v = ((const float4*)x)[i];
        o2[i*2+0] = __floats2half2_rn(v.x, v.y);
        o2[i*2+1] = __floats2half2_rn(v.z, v.w);
    }
}

// ---------------- W[K,N] -> WT[N,K] f16 transpose ----------------
__global__ void ttrans_kernel(const float* __restrict__ W,
                              __half* __restrict__ T, int K, int N) {
    __shared__ float t[32][33];
    int x = blockIdx.x*32 + threadIdx.x;
#pragma unroll
    for (int j = 0; j < 4; j++) {
        int y = blockIdx.y*32 + threadIdx.y + j*8;
        t[threadIdx.y + j*8][threadIdx.x] = W[(size_t)y*N + x];
    }
    __syncthreads();
    int xo = blockIdx.y*32 + threadIdx.x;
#pragma unroll
    for (int j = 0; j < 4; j++) {
        int yo = blockIdx.x*32 + threadIdx.y + j*8;
        T[(size_t)yo*K + xo] = __float2half_rn(t[threadIdx.x][threadIdx.y + j*8]);
    }
}

// ---------------- bias concat bq||bk||bv ----------------
__global__ void bqkv_kernel(const float* __restrict__ bq,
                            const float* __restrict__ bk,
                            const float* __restrict__ bv) {
    int i = blockIdx.x*blockDim.x + threadIdx.x;
    if (i < NQKV)
        g_bqkv[i] = (i < 2048) ? bq[i] : (i < 2176 ? bk[i-2048] : bv[i-2176]);
}

// ---------------- V fp32 -> VT[b][d][s] f16 transpose ----------------
__global__ void vtrans_kernel() {
    __shared__ float t[32][33];
    int b  = blockIdx.z;
    int s0 = blockIdx.x*32;
    int d0 = blockIdx.y*32;
#pragma unroll
    for (int j = 0; j < 4; j++) {
        int s = s0 + threadIdx.y + j*8;
        t[threadIdx.y + j*8][threadIdx.x] = g_V[((size_t)b*SEQ + s)*HD + d0 + threadIdx.x];
    }
    __syncthreads();
#pragma unroll
    for (int j = 0; j < 4; j++) {
        int d = d0 + threadIdx.y + j*8;
        g_VTh[((size_t)b*HD + d)*SEQ + s0 + threadIdx.x] =
            __float2half_rn(t[threadIdx.x][threadIdx.y + j*8]);
    }
}

// ---------------- mma.sync f16 GEMM ----------------
// C[M,N] = A@B^T + bias ; A[M,K] f16, B[N,K] f16 K-major.
// EPI=0: fp32 out to C (Oproj). EPI=1: fused QKV epilogue
//   n0<2048 -> Qf f16 (scaled); n0==2048 -> Kf f16; n0==2176 -> Vf fp32.
template<int EPI>
__global__ __launch_bounds__(256, 2) void gemm_mma_kernel(
    const __half* __restrict__ A, const __half* __restrict__ B,
    const float* __restrict__ bias, float* __restrict__ C,
    __half* __restrict__ Qf, __half* __restrict__ Kf, float* __restrict__ Vf,
    float oscale, int M, int N, int K)
{
    extern __shared__ char dyn[];
    const int tid  = threadIdx.x;
    const int warp = tid >> 5;
    const int lane = tid & 31;
    const int wm   = warp >> 2;
    const int wn   = warp & 3;
    const int n0 = blockIdx.x * 128;
    const int m0 = blockIdx.y * 128;

    const uint32_t sbase = (smem_u32(dyn) + 1023u) & ~1023u;

    float acc[4][4][4];
#pragma unroll
    for (int mt = 0; mt < 4; mt++)
#pragma unroll
        for (int nt = 0; nt < 4; nt++)
#pragma unroll
            for (int q = 0; q < 4; q++) acc[mt][nt][q] = 0.f;

    auto stage = [&](uint32_t tb, int k0) {
#pragma unroll
        for (int u = tid; u < 2048; u += 256) {
            int t   = u >> 10;
            int idx = u & 1023;
            int row = idx >> 3;
            int c16 = idx & 7;
            const __half* src = t ? (B + (size_t)(n0+row)*K + k0 + c16*8)
                                  : (A + (size_t)(m0+row)*K + k0 + c16*8);
            cp16(tb + t*16384 + SW128((uint32_t)(row*128 + c16*16)), src);
        }
        asm volatile("cp.async.commit_group;" ::: "memory");
    };

    const int nch = K / 64;
    stage(sbase, 0);

    for (int ch = 0; ch < nch; ch++) {
        if (ch + 1 < nch) {
            stage(sbase + ((ch+1)&1)*CHUNK_BYTES, (ch+1)*64);
            asm volatile("cp.async.wait_group 1;" ::: "memory");
        } else {
            asm volatile("cp.async.wait_group 0;" ::: "memory");
        }
        __syncthreads();

        const uint32_t tb = sbase + (ch&1)*CHUNK_BYTES;
        const uint32_t tA = tb, tB = tb + 16384;

#pragma unroll
        for (int ks = 0; ks < 4; ks++) {
            uint32_t ah[4][4], bh[2][4];
            const uint32_t abyte = (uint32_t)(ks*32 + (lane>>4)*16);
            const int      arow  = wm*64 + (lane & 15);
#pragma unroll
            for (int mt = 0; mt < 4; mt++)
                ldsm4(ah[mt], tA + SW128((uint32_t)((arow + mt*16)*128) + abyte));
            const uint32_t bbyte = (uint32_t)(ks*32 + ((lane>>3)&1)*16);
            const int      brow  = wn*32 + (lane & 7) + (lane>>4)*8;
#pragma unroll
            for (int np = 0; np < 2; np++)
                ldsm4(bh[np], tB + SW128((uint32_t)((brow + np*16)*128) + bbyte));
#pragma unroll
            for (int mt = 0; mt < 4; mt++)
#pragma unroll
                for (int nt = 0; nt < 4; nt++)
                    mma16816(acc[mt][nt], ah[mt], &bh[nt>>1][(nt&1)*2]);
        }
        __syncthreads();
    }

    const int g  = lane >> 2;
    const int tg = lane & 3;
#pragma unroll
    for (int mt = 0; mt < 4; mt++) {
        const int r0 = m0 + wm*64 + mt*16 + g;
#pragma unroll
        for (int nt = 0; nt < 4; nt++) {
            const int col = n0 + wn*32 + nt*8 + tg*2;
            const float b0 = bias[col], b1 = bias[col+1];
            float v0 = acc[mt][nt][0] + b0, v1 = acc[mt][nt][1] + b1;
            float v2 = acc[mt][nt][2] + b0, v3 = acc[mt][nt][3] + b1;
            if (EPI == 0) {
                *(float2*)&C[(size_t)r0*N + col]     = make_float2(v0, v1);
                *(float2*)&C[(size_t)(r0+8)*N + col] = make_float2(v2, v3);
            } else {
                if (n0 < 2048) {           // Q: f16 scaled
                    *(uint32_t*)&Qf[(size_t)r0*HID + col] =
                        pack_f16(v0*oscale, v1*oscale);
                    *(uint32_t*)&Qf[(size_t)(r0+8)*HID + col] =
                        pack_f16(v2*oscale, v3*oscale);
                } else if (n0 < 2176) {    // K: f16
                    const int d = col - 2048;
                    *(uint32_t*)&Kf[(size_t)r0*HD + d]     = pack_f16(v0, v1);
                    *(uint32_t*)&Kf[(size_t)(r0+8)*HD + d] = pack_f16(v2, v3);
                } else {                   // V: fp32 (pre-transpose)
                    const int d = col - 2176;
                    *(float2*)&Vf[(size_t)r0*HD + d]     = make_float2(v0, v1);
                    *(float2*)&Vf[(size_t)(r0+8)*HD + d] = make_float2(v2, v3);
                }
            }
        }
    }
}

// ---------------- mma.sync flash attention (single f16) ----------------
// grid (SEQ/128, NH, BATCH), 256 threads (8 warps x 16 q-rows).
__global__ __launch_bounds__(256) void attn_mma_kernel(const int* __restrict__ mask)
{
    extern __shared__ char dyn[];
    const int tid  = threadIdx.x;
    const int warp = tid >> 5;
    const int lane = tid & 31;
    const int g    = lane >> 2;
    const int tg   = lane & 3;
    const int h  = blockIdx.y;
    const int b  = blockIdx.z;
    const int q0 = blockIdx.x * 128;
    const int allones = g_allones;

    const uint32_t base = (smem_u32(dyn) + 1023u) & ~1023u;
    const uint32_t sQ   = base;                 // Q f16: chunk0@0, chunk1@16384
    const uint32_t sKV0 = base + 32768;         // per buf (32KB): K@0, VT@16384

    // ---- stage Q (once) ----
    for (int u = tid; u < 2048; u += 256) {
        int chunk = u >> 10, r = (u >> 3) & 127, c16 = u & 7;
        const __half* src =
            g_Qh + ((size_t)(b*SEQ + q0 + r))*HID + h*HD + chunk*64 + c16*8;
        cp16(sQ + chunk*16384 + SW128((uint32_t)(r*128 + c16*16)), src);
    }

    auto stageKV = [&](uint32_t bb, int j0) {
#pragma unroll
        for (int u = tid; u < 1024; u += 256) {   // K tile [64 tok][128 d]
            int chunk = u >> 9, r = (u >> 3) & 63, c16 = u & 7;
            const __half* src =
                g_Kh + ((size_t)(b*SEQ + j0 + r))*HD + chunk*64 + c16*8;
            cp16(bb + chunk*8192 + SW128((uint32_t)(r*128 + c16*16)), src);
        }
#pragma unroll
        for (int u = tid; u < 1024; u += 256) {   // VT tile [128 d][64 tok]
            int r = u >> 3, c16 = u & 7;
            const __half* src = g_VTh + ((size_t)b*HD + r)*SEQ + j0 + c16*8;
            cp16(bb + 16384 + SW128((uint32_t)(r*128 + c16*16)), src);
        }
        asm volatile("cp.async.commit_group;" ::: "memory");
    };

    stageKV(sKV0, 0);

    float m0r = -1e30f, m1r = -1e30f, l0r = 0.f, l1r = 0.f;
    float o[16][4];
#pragma unroll
    for (int nt = 0; nt < 16; nt++)
#pragma unroll
        for (int e = 0; e < 4; e++) o[nt][e] = 0.f;

    const int NT = SEQ / BKV;
    for (int t = 0; t < NT; t++) {
        if (t + 1 < NT) {
            stageKV(sKV0 + ((t+1)&1)*32768, (t+1)*BKV);
            asm volatile("cp.async.wait_group 1;" ::: "memory");
        } else {
            asm volatile("cp.async.wait_group 0;" ::: "memory");
        }
        __syncthreads();

        const uint32_t bb = sKV0 + (t&1)*32768;
        const uint32_t kh = bb, vh = bb + 16384;
        const int j0 = t * BKV;

        // ---- scores S[16, 64] = Q @ K^T ----
        float s[8][4];
#pragma unroll
        for (int nt = 0; nt < 8; nt++)
#pragma unroll
            for (int e = 0; e < 4; e++) s[nt][e] = 0.f;

#pragma unroll
        for (int ks = 0; ks < 8; ks++) {
            uint32_t aH[4];
            uint32_t aoff = (ks>>2)*16384 +
                SW128((uint32_t)((warp*16 + (lane & 15))*128 + (ks&3)*32 + (lane>>4)*16));
            ldsm4(aH, sQ + aoff);
#pragma unroll
            for (int np = 0; np < 4; np++) {
                uint32_t bH[4];
                uint32_t boff = (ks>>2)*8192 +
                    SW128((uint32_t)((np*16 + (lane&7) + (lane>>4)*8)*128
                                     + (ks&3)*32 + ((lane>>3)&1)*16));
                ldsm4(bH, kh + boff);
                mma16816(s[2*np],   aH, &bH[0]);
                mma16816(s[2*np+1], aH, &bH[2]);
            }
        }

        if (!allones) {
#pragma unroll
            for (int nt = 0; nt < 8; nt++)
#pragma unroll
                for (int e = 0; e < 4; e++) {
                    int qr = q0 + warp*16 + g + ((e>>1)<<3);
                    int kc = j0 + nt*8 + tg*2 + (e&1);
                    if (mask[((size_t)b*SEQ + qr)*SEQ + kc] == 0) s[nt][e] = -1e30f;
                }
        }

        // ---- online softmax (rows g, g+8; quad lanes share a row) ----
        float rm0 = s[0][0], rm1 = s[0][2];
#pragma unroll
        for (int nt = 0; nt < 8; nt++) {
            rm0 = fmaxf(rm0, fmaxf(s[nt][0], s[nt][1]));
            rm1 = fmaxf(rm1, fmaxf(s[nt][2], s[nt][3]));
        }
        rm0 = fmaxf(rm0, __shfl_xor_sync(0xffffffffu, rm0, 1));
        rm0 = fmaxf(rm0, __shfl_xor_sync(0xffffffffu, rm0, 2));
        rm1 = fmaxf(rm1, __shfl_xor_sync(0xffffffffu, rm1, 1));
        rm1 = fmaxf(rm1, __shfl_xor_sync(0xffffffffu, rm1, 2));
        float mn0 = fmaxf(m0r, rm0), mn1 = fmaxf(m1r, rm1);
        float c0 = __expf(m0r - mn0), c1 = __expf(m1r - mn1);
        float rs0 = 0.f, rs1 = 0.f;
#pragma unroll
        for (int nt = 0; nt < 8; nt++) {
            s[nt][0] = __expf(s[nt][0] - mn0);
            s[nt][1] = __expf(s[nt][1] - mn0);
            s[nt][2] = __expf(s[nt][2] - mn1);
            s[nt][3] = __expf(s[nt][3] - mn1);
            rs0 += s[nt][0] + s[nt][1];
            rs1 += s[nt][2] + s[nt][3];
        }
        rs0 += __shfl_xor_sync(0xffffffffu, rs0, 1);
        rs0 += __shfl_xor_sync(0xffffffffu, rs0, 2);
        rs1 += __shfl_xor_sync(0xffffffffu, rs1, 1);
        rs1 += __shfl_xor_sync(0xffffffffu, rs1, 2);
        m0r = mn0; m1r = mn1;
        l0r = l0r*c0 + rs0;
        l1r = l1r*c1 + rs1;
#pragma unroll
        for (int nt = 0; nt < 16; nt++) {
            o[nt][0] *= c0; o[nt][1] *= c0;
            o[nt][2] *= c1; o[nt][3] *= c1;
        }

        // ---- P.V : O[16, 128] += P[16, 64] @ VT^T ----
#pragma unroll
        for (int kg = 0; kg < 4; kg++) {
            uint32_t aP[4];
            aP[0] = pack_f16(s[2*kg][0],   s[2*kg][1]);
            aP[1] = pack_f16(s[2*kg][2],   s[2*kg][3]);
            aP[2] = pack_f16(s[2*kg+1][0], s[2*kg+1][1]);
            aP[3] = pack_f16(s[2*kg+1][2], s[2*kg+1][3]);
#pragma unroll
            for (int np = 0; np < 8; np++) {
                uint32_t bH[4];
                uint32_t boff =
                    SW128((uint32_t)((np*16 + (lane&7) + (lane>>4)*8)*128
                                     + kg*32 + ((lane>>3)&1)*16));
                ldsm4(bH, vh + boff);
                mma16816(o[2*np],   aP, &bH[0]);
                mma16816(o[2*np+1], aP, &bH[2]);
            }
        }
        __syncthreads();
    }

    // ---- epilogue: O/l -> f16 into g_Ah ----
    float inv0 = 1.f / l0r, inv1 = 1.f / l1r;
    const size_t r0 = (size_t)(b*SEQ + q0 + warp*16 + g);
    const size_t r1 = r0 + 8;
#pragma unroll
    for (int nt = 0; nt < 16; nt++) {
        const int col = h*HD + nt*8 + tg*2;
        *(uint32_t*)&g_Ah[r0*HID + col] = pack_f16(o[nt][0]*inv0, o[nt][1]*inv0);
        *(uint32_t*)&g_Ah[r1*HID + col] = pack_f16(o[nt][2]*inv1, o[nt][3]*inv1);
    }
}

// ---------------- launch ----------------
extern "C" void kernel_launch(void* const* d_in, const int* in_sizes, int n_in,
                              void* d_out, int out_size)
{
    const float* X  = (const float*)d_in[0];
    const int* mask = (const int*)  d_in[1];
    const float* Wq = (const float*)d_in[2];
    const float* bq = (const float*)d_in[3];
    const float* Wk = (const float*)d_in[4];
    const float* bk = (const float*)d_in[5];
    const float* Wv = (const float*)d_in[6];
    const float* bv = (const float*)d_in[7];
    const float* Wo = (const float*)d_in[8];
    const float* bo = (const float*)d_in[9];
    float* out = (float*)d_out;

    float *vp, *bqkvp;
    cudaGetSymbolAddress((void**)&vp,    g_V);
    cudaGetSymbolAddress((void**)&bqkvp, g_bqkv);

    __half *xh, *qh, *ah, *kh, *wt, *wot;
    cudaGetSymbolAddress((void**)&xh,  g_Xh);
    cudaGetSymbolAddress((void**)&qh,  g_Qh);
    cudaGetSymbolAddress((void**)&ah,  g_Ah);
    cudaGetSymbolAddress((void**)&kh,  g_Kh);
    cudaGetSymbolAddress((void**)&wt,  g_WT);
    cudaGetSymbolAddress((void**)&wot, g_WoT);

    cudaFuncSetAttribute(gemm_mma_kernel<0>,
                         cudaFuncAttributeMaxDynamicSharedMemorySize, GEMM_DYN);
    cudaFuncSetAttribute(gemm_mma_kernel<1>,
                         cudaFuncAttributeMaxDynamicSharedMemorySize, GEMM_DYN);
    cudaFuncSetAttribute(attn_mma_kernel,
                         cudaFuncAttributeMaxDynamicSharedMemorySize, ATTN_DYN);

    const float scale = 0.088388347648318447f;  // 1/sqrt(128)

    // Launch order: fused projection GEMM is the 6th launch (ncu -s 5 -c 1).
    xhalf_kernel<<<4096, 256>>>(X, xh, MTOT*HID/4);                         // 1
    ttrans_kernel<<<dim3(HID/32, HID/32), dim3(32,8)>>>(Wq, wt, HID, HID);  // 2
    ttrans_kernel<<<dim3(HD/32,  HID/32), dim3(32,8)>>>(                    // 3
        Wk, wt + (size_t)2048*HID, HID, HD);
    ttrans_kernel<<<dim3(HD/32,  HID/32), dim3(32,8)>>>(                    // 4
        Wv, wt + (size_t)2176*HID, HID, HD);
    bqkv_kernel<<<9, 256>>>(bq, bk, bv);                                    // 5
    gemm_mma_kernel<1><<<dim3(NQKV/128, MTOT/128), 256, GEMM_DYN>>>(        // 6 (profiled)
        xh, wt, bqkvp, nullptr, qh, kh, vp, scale, MTOT, NQKV, HID);

    flag_init_kernel<<<1, 1>>>();                                           // 7
    mask_scan_kernel<<<512, 256>>>(mask);                                   // 8
    vtrans_kernel<<<dim3(SEQ/32, HD/32, BATCH), dim3(32,8)>>>();            // 9
    attn_mma_kernel<<<dim3(SEQ/128, NH, BATCH), 256, ATTN_DYN>>>(mask);     // 10
    ttrans_kernel<<<dim3(HID/32, HID/32), dim3(32,8)>>>(Wo, wot, HID, HID); // 11
    gemm_mma_kernel<0><<<dim3(HID/128, MTOT/128), 256, GEMM_DYN>>>(         // 12
        ah, wot, bo, out, nullptr, nullptr, nullptr, 1.f, MTOT, HID, HID);
}

// round 8
// speedup vs baseline: 14.1776x; 1.0184x over previous
#include <cuda_runtime.h>
#include <cuda_fp16.h>
#include <cstdint>
#include <math.h>

#define BATCH 2
#define SEQ   2048
#define HID   2048
#define NH    16
#define HD    128
#define MTOT  (BATCH*SEQ)
#define NQKV  2304   // 2048 (Q) + 128 (K) + 128 (V)

// ---------------- mma GEMM config (single f16, 3-stage pipeline) ----------------
#define CHUNK_BYTES 32768           // 2 tiles x 128rows x 128B (A, B)
#define GEMM_DYN    (3*CHUNK_BYTES + 1024)

// ---------------- mma attention config ----------------
#define BKV 64
#define ATTN_DYN (32768 + 2*32768 + 1024)  // Q(32KB) + 2 KV bufs(32KB each)

// ---------------- device scratch ----------------
__device__ float  g_V[(size_t)MTOT*HD];     // V projection (fp32, pre-transpose)
__device__ int    g_anyzero = 0;            // sticky: any mask element == 0

__device__ __half g_Xh [(size_t)MTOT*HID];
__device__ __half g_Qh [(size_t)MTOT*HID];
__device__ __half g_Ah [(size_t)MTOT*HID];
__device__ __half g_Kh [(size_t)MTOT*HD];
__device__ __half g_VTh[(size_t)BATCH*HD*SEQ];
__device__ __half g_WT [(size_t)NQKV*HID];  // rows: WqT(0-2047) WkT(2048-2175) WvT(2176-2303)
__device__ __half g_WoT[(size_t)HID*HID];
__device__ float  g_bqkv[NQKV];

// ---------------- helpers ----------------
__device__ __forceinline__ uint32_t smem_u32(const void* p) {
    uint32_t a;
    asm("{ .reg .u64 t; cvta.to.shared.u64 t, %1; cvt.u32.u64 %0, t; }" : "=r"(a) : "l"(p));
    return a;
}
__device__ __forceinline__ void cp16(uint32_t dst, const void* src) {
    asm volatile("cp.async.cg.shared.global [%0], [%1], 16;" :: "r"(dst), "l"(src));
}
__device__ __forceinline__ void ldsm4(uint32_t* r, uint32_t addr) {
    asm volatile("ldmatrix.sync.aligned.m8n8.x4.shared.b16 {%0,%1,%2,%3}, [%4];"
                 : "=r"(r[0]), "=r"(r[1]), "=r"(r[2]), "=r"(r[3]) : "r"(addr));
}
__device__ __forceinline__ void mma16816(float* c, const uint32_t* a, const uint32_t* b) {
    asm volatile(
        "mma.sync.aligned.m16n8k16.row.col.f32.f16.f16.f32 "
        "{%0,%1,%2,%3}, {%4,%5,%6,%7}, {%8,%9}, {%0,%1,%2,%3};"
        : "+f"(c[0]), "+f"(c[1]), "+f"(c[2]), "+f"(c[3])
        : "r"(a[0]), "r"(a[1]), "r"(a[2]), "r"(a[3]), "r"(b[0]), "r"(b[1]));
}
// packed f16x2: lo in lower half, hi in upper half
__device__ __forceinline__ uint32_t pack_f16(float lo, float hi) {
    uint32_t r;
    asm("cvt.rn.f16x2.f32 %0, %1, %2;" : "=r"(r) : "f"(hi), "f"(lo));
    return r;
}
#define SW128(x) ((x) ^ (((x) >> 3) & 0x70))

// ---------------- fused prep kernel ----------------
// Block partition (256 threads each):
//   [0,1024)      xhalf: X fp32 -> Xh f16            (grid-stride)
//   [1024,5120)   ttrans Wq -> WT rows 0-2047
//   [5120,5376)   ttrans Wk -> WT rows 2048-2175
//   [5376,5632)   ttrans Wv -> WT rows 2176-2303
//   [5632,5641)   bqkv concat
//   [5641,9737)   ttrans Wo -> WoT
//   [9737,10249)  mask scan -> g_anyzero
#define PREP_BLOCKS 10249

__device__ __forceinline__ void ttrans_job(const float* __restrict__ W,
                                           __half* __restrict__ T,
                                           int K, int N, int bx, int by,
                                           float (*t)[33]) {
    int x = bx*32 + threadIdx.x;
    int ty = threadIdx.y;          // via tid decomposition below
    (void)ty;
    int tyy = (threadIdx.x >> 5);  // unused placeholder
    (void)tyy;
    // 256 threads = 32 x 8 layout
    int lx = threadIdx.x & 31;
    int ly = threadIdx.x >> 5;     // 0..7
    x = bx*32 + lx;
#pragma unroll
    for (int j = 0; j < 4; j++) {
        int y = by*32 + ly + j*8;
        t[ly + j*8][lx] = W[(size_t)y*N + x];
    }
    __syncthreads();
    int xo = by*32 + lx;
#pragma unroll
    for (int j = 0; j < 4; j++) {
        int yo = bx*32 + ly + j*8;
        T[(size_t)yo*K + xo] = __float2half_rn(t[lx][ly + j*8]);
    }
}

__global__ __launch_bounds__(256) void prep_kernel(
    const float* __restrict__ X, const int* __restrict__ mask,
    const float* __restrict__ Wq, const float* __restrict__ Wk,
    const float* __restrict__ Wv, const float* __restrict__ Wo,
    const float* __restrict__ bq, const float* __restrict__ bk,
    const float* __restrict__ bv)
{
    __shared__ float t[32][33];
    const int bid = blockIdx.x;
    const int tid = threadIdx.x;

    if (bid < 1024) {                       // xhalf
        const int n4 = MTOT*HID/4;
        __half2* o2 = (__half2*)g_Xh;
        for (int i = bid*256 + tid; i < n4; i += 1024*256) {
            float4 v = ((const float4*)X)[i];
            o2[i*2+0] = __floats2half2_rn(v.x, v.y);
            o2[i*2+1] = __floats2half2_rn(v.z, v.w);
        }
    } else if (bid < 5120) {                // Wq transpose
        int i = bid - 1024;
        ttrans_job(Wq, g_WT, HID, HID, i & 63, i >> 6, t);
    } else if (bid < 5376) {                // Wk transpose
        int i = bid - 5120;
        ttrans_job(Wk, g_WT + (size_t)2048*HID, HID, HD, i & 3, i >> 2, t);
    } else if (bid < 5632) {                // Wv transpose
        int i = bid - 5376;
        ttrans_job(Wv, g_WT + (size_t)2176*HID, HID, HD, i & 3, i >> 2, t);
    } else if (bid < 5641) {                // bqkv concat
        int i = (bid - 5632)*256 + tid;
        if (i < NQKV)
            g_bqkv[i] = (i < 2048) ? bq[i] : (i < 2176 ? bk[i-2048] : bv[i-2176]);
    } else if (bid < 9737) {                // Wo transpose
        int i = bid - 5641;
        ttrans_job(Wo, g_WoT, HID, HID, i & 63, i >> 6, t);
    } else {                                // mask scan
        int base = bid - 9737;
        const int4* m4 = (const int4*)mask;
        const int total = BATCH*SEQ*SEQ/4;
        int bad = 0;
        for (int i = base*256 + tid; i < total; i += 512*256) {
            int4 v = m4[i];
            if ((v.x == 0) | (v.y == 0) | (v.z == 0) | (v.w == 0)) bad = 1;
        }
        if (bad) g_anyzero = 1;
    }
}

// ---------------- V fp32 -> VT[b][d][s] f16 transpose ----------------
__global__ void vtrans_kernel() {
    __shared__ float t[32][33];
    int b  = blockIdx.z;
    int s0 = blockIdx.x*32;
    int d0 = blockIdx.y*32;
#pragma unroll
    for (int j = 0; j < 4; j++) {
        int s = s0 + threadIdx.y + j*8;
        t[threadIdx.y + j*8][threadIdx.x] = g_V[((size_t)b*SEQ + s)*HD + d0 + threadIdx.x];
    }
    __syncthreads();
#pragma unroll
    for (int j = 0; j < 4; j++) {
        int d = d0 + threadIdx.y + j*8;
        g_VTh[((size_t)b*HD + d)*SEQ + s0 + threadIdx.x] =
            __float2half_rn(t[threadIdx.x][threadIdx.y + j*8]);
    }
}

// ---------------- mma.sync f16 GEMM (3-stage pipeline) ----------------
// C[M,N] = A@B^T + bias ; A[M,K] f16, B[N,K] f16 K-major.
// EPI=0: fp32 out to C (Oproj). EPI=1: fused QKV epilogue.
template<int EPI>
__global__ __launch_bounds__(256, 2) void gemm_mma_kernel(
    const __half* __restrict__ A, const __half* __restrict__ B,
    const float* __restrict__ bias, float* __restrict__ C,
    __half* __restrict__ Qf, __half* __restrict__ Kf, float* __restrict__ Vf,
    float oscale, int M, int N, int K)
{
    extern __shared__ char dyn[];
    const int tid  = threadIdx.x;
    const int warp = tid >> 5;
    const int lane = tid & 31;
    const int wm   = warp >> 2;
    const int wn   = warp & 3;
    const int n0 = blockIdx.x * 128;
    const int m0 = blockIdx.y * 128;

    const uint32_t sbase = (smem_u32(dyn) + 1023u) & ~1023u;

    float acc[4][4][4];
#pragma unroll
    for (int mt = 0; mt < 4; mt++)
#pragma unroll
        for (int nt = 0; nt < 4; nt++)
#pragma unroll
            for (int q = 0; q < 4; q++) acc[mt][nt][q] = 0.f;

    auto stage = [&](uint32_t tb, int k0) {
#pragma unroll
        for (int u = tid; u < 2048; u += 256) {
            int t   = u >> 10;
            int idx = u & 1023;
            int row = idx >> 3;
            int c16 = idx & 7;
            const __half* src = t ? (B + (size_t)(n0+row)*K + k0 + c16*8)
                                  : (A + (size_t)(m0+row)*K + k0 + c16*8);
            cp16(tb + t*16384 + SW128((uint32_t)(row*128 + c16*16)), src);
        }
        asm volatile("cp.async.commit_group;" ::: "memory");
    };

    const int nch = K / 64;
    stage(sbase, 0);
    if (nch > 1) stage(sbase + CHUNK_BYTES, 64);

    for (int ch = 0; ch < nch; ch++) {
        if (ch + 2 < nch) {
            stage(sbase + ((ch+2)%3)*CHUNK_BYTES, (ch+2)*64);
            asm volatile("cp.async.wait_group 2;" ::: "memory");
        } else if (ch + 1 < nch) {
            asm volatile("cp.async.wait_group 1;" ::: "memory");
        } else {
            asm volatile("cp.async.wait_group 0;" ::: "memory");
        }
        __syncthreads();

        const uint32_t tb = sbase + (ch%3)*CHUNK_BYTES;
        const uint32_t tA = tb, tB = tb + 16384;

#pragma unroll
        for (int ks = 0; ks < 4; ks++) {
            uint32_t ah[4][4], bh[2][4];
            const uint32_t abyte = (uint32_t)(ks*32 + (lane>>4)*16);
            const int      arow  = wm*64 + (lane & 15);
#pragma unroll
            for (int mt = 0; mt < 4; mt++)
                ldsm4(ah[mt], tA + SW128((uint32_t)((arow + mt*16)*128) + abyte));
            const uint32_t bbyte = (uint32_t)(ks*32 + ((lane>>3)&1)*16);
            const int      brow  = wn*32 + (lane & 7) + (lane>>4)*8;
#pragma unroll
            for (int np = 0; np < 2; np++)
                ldsm4(bh[np], tB + SW128((uint32_t)((brow + np*16)*128) + bbyte));
#pragma unroll
            for (int mt = 0; mt < 4; mt++)
#pragma unroll
                for (int nt = 0; nt < 4; nt++)
                    mma16816(acc[mt][nt], ah[mt], &bh[nt>>1][(nt&1)*2]);
        }
        __syncthreads();
    }

    const int g  = lane >> 2;
    const int tg = lane & 3;
#pragma unroll
    for (int mt = 0; mt < 4; mt++) {
        const int r0 = m0 + wm*64 + mt*16 + g;
#pragma unroll
        for (int nt = 0; nt < 4; nt++) {
            const int col = n0 + wn*32 + nt*8 + tg*2;
            const float b0 = bias[col], b1 = bias[col+1];
            float v0 = acc[mt][nt][0] + b0, v1 = acc[mt][nt][1] + b1;
            float v2 = acc[mt][nt][2] + b0, v3 = acc[mt][nt][3] + b1;
            if (EPI == 0) {
                *(float2*)&C[(size_t)r0*N + col]     = make_float2(v0, v1);
                *(float2*)&C[(size_t)(r0+8)*N + col] = make_float2(v2, v3);
            } else {
                if (n0 < 2048) {           // Q: f16 scaled
                    *(uint32_t*)&Qf[(size_t)r0*HID + col] =
                        pack_f16(v0*oscale, v1*oscale);
                    *(uint32_t*)&Qf[(size_t)(r0+8)*HID + col] =
                        pack_f16(v2*oscale, v3*oscale);
                } else if (n0 < 2176) {    // K: f16
                    const int d = col - 2048;
                    *(uint32_t*)&Kf[(size_t)r0*HD + d]     = pack_f16(v0, v1);
                    *(uint32_t*)&Kf[(size_t)(r0+8)*HD + d] = pack_f16(v2, v3);
                } else {                   // V: fp32 (pre-transpose)
                    const int d = col - 2176;
                    *(float2*)&Vf[(size_t)r0*HD + d]     = make_float2(v0, v1);
                    *(float2*)&Vf[(size_t)(r0+8)*HD + d] = make_float2(v2, v3);
                }
            }
        }
    }
}

// ---------------- mma.sync flash attention (single f16) ----------------
// grid (SEQ/128, NH, BATCH), 256 threads (8 warps x 16 q-rows).
__global__ __launch_bounds__(256) void attn_mma_kernel(const int* __restrict__ mask)
{
    extern __shared__ char dyn[];
    const int tid  = threadIdx.x;
    const int warp = tid >> 5;
    const int lane = tid & 31;
    const int g    = lane >> 2;
    const int tg   = lane & 3;
    const int h  = blockIdx.y;
    const int b  = blockIdx.z;
    const int q0 = blockIdx.x * 128;
    const int allones = (g_anyzero == 0);

    const uint32_t base = (smem_u32(dyn) + 1023u) & ~1023u;
    const uint32_t sQ   = base;                 // Q f16: chunk0@0, chunk1@16384
    const uint32_t sKV0 = base + 32768;         // per buf (32KB): K@0, VT@16384

    // ---- stage Q (once) ----
    for (int u = tid; u < 2048; u += 256) {
        int chunk = u >> 10, r = (u >> 3) & 127, c16 = u & 7;
        const __half* src =
            g_Qh + ((size_t)(b*SEQ + q0 + r))*HID + h*HD + chunk*64 + c16*8;
        cp16(sQ + chunk*16384 + SW128((uint32_t)(r*128 + c16*16)), src);
    }

    auto stageKV = [&](uint32_t bb, int j0) {
#pragma unroll
        for (int u = tid; u < 1024; u += 256) {   // K tile [64 tok][128 d]
            int chunk = u >> 9, r = (u >> 3) & 63, c16 = u & 7;
            const __half* src =
                g_Kh + ((size_t)(b*SEQ + j0 + r))*HD + chunk*64 + c16*8;
            cp16(bb + chunk*8192 + SW128((uint32_t)(r*128 + c16*16)), src);
        }
#pragma unroll
        for (int u = tid; u < 1024; u += 256) {   // VT tile [128 d][64 tok]
            int r = u >> 3, c16 = u & 7;
            const __half* src = g_VTh + ((size_t)b*HD + r)*SEQ + j0 + c16*8;
            cp16(bb + 16384 + SW128((uint32_t)(r*128 + c16*16)), src);
        }
        asm volatile("cp.async.commit_group;" ::: "memory");
    };

    stageKV(sKV0, 0);

    float m0r = -1e30f, m1r = -1e30f, l0r = 0.f, l1r = 0.f;
    float o[16][4];
#pragma unroll
    for (int nt = 0; nt < 16; nt++)
#pragma unroll
        for (int e = 0; e < 4; e++) o[nt][e] = 0.f;

    const int NT = SEQ / BKV;
    for (int t = 0; t < NT; t++) {
        if (t + 1 < NT) {
            stageKV(sKV0 + ((t+1)&1)*32768, (t+1)*BKV);
            asm volatile("cp.async.wait_group 1;" ::: "memory");
        } else {
            asm volatile("cp.async.wait_group 0;" ::: "memory");
        }
        __syncthreads();

        const uint32_t bb = sKV0 + (t&1)*32768;
        const uint32_t kh = bb, vh = bb + 16384;
        const int j0 = t * BKV;

        // ---- scores S[16, 64] = Q @ K^T ----
        float s[8][4];
#pragma unroll
        for (int nt = 0; nt < 8; nt++)
#pragma unroll
            for (int e = 0; e < 4; e++) s[nt][e] = 0.f;

#pragma unroll
        for (int ks = 0; ks < 8; ks++) {
            uint32_t aH[4];
            uint32_t aoff = (ks>>2)*16384 +
                SW128((uint32_t)((warp*16 + (lane & 15))*128 + (ks&3)*32 + (lane>>4)*16));
            ldsm4(aH, sQ + aoff);
#pragma unroll
            for (int np = 0; np < 4; np++) {
                uint32_t bH[4];
                uint32_t boff = (ks>>2)*8192 +
                    SW128((uint32_t)((np*16 + (lane&7) + (lane>>4)*8)*128
                                     + (ks&3)*32 + ((lane>>3)&1)*16));
                ldsm4(bH, kh + boff);
                mma16816(s[2*np],   aH, &bH[0]);
                mma16816(s[2*np+1], aH, &bH[2]);
            }
        }

        if (!allones) {
#pragma unroll
            for (int nt = 0; nt < 8; nt++)
#pragma unroll
                for (int e = 0; e < 4; e++) {
                    int qr = q0 + warp*16 + g + ((e>>1)<<3);
                    int kc = j0 + nt*8 + tg*2 + (e&1);
                    if (mask[((size_t)b*SEQ + qr)*SEQ + kc] == 0) s[nt][e] = -1e30f;
                }
        }

        // ---- online softmax (rows g, g+8; quad lanes share a row) ----
        float rm0 = s[0][0], rm1 = s[0][2];
#pragma unroll
        for (int nt = 0; nt < 8; nt++) {
            rm0 = fmaxf(rm0, fmaxf(s[nt][0], s[nt][1]));
            rm1 = fmaxf(rm1, fmaxf(s[nt][2], s[nt][3]));
        }
        rm0 = fmaxf(rm0, __shfl_xor_sync(0xffffffffu, rm0, 1));
        rm0 = fmaxf(rm0, __shfl_xor_sync(0xffffffffu, rm0, 2));
        rm1 = fmaxf(rm1, __shfl_xor_sync(0xffffffffu, rm1, 1));
        rm1 = fmaxf(rm1, __shfl_xor_sync(0xffffffffu, rm1, 2));
        float mn0 = fmaxf(m0r, rm0), mn1 = fmaxf(m1r, rm1);
        float c0 = __expf(m0r - mn0), c1 = __expf(m1r - mn1);
        float rs0 = 0.f, rs1 = 0.f;
#pragma unroll
        for (int nt = 0; nt < 8; nt++) {
            s[nt][0] = __expf(s[nt][0] - mn0);
            s[nt][1] = __expf(s[nt][1] - mn0);
            s[nt][2] = __expf(s[nt][2] - mn1);
            s[nt][3] = __expf(s[nt][3] - mn1);
            rs0 += s[nt][0] + s[nt][1];
            rs1 += s[nt][2] + s[nt][3];
        }
        rs0 += __shfl_xor_sync(0xffffffffu, rs0, 1);
        rs0 += __shfl_xor_sync(0xffffffffu, rs0, 2);
        rs1 += __shfl_xor_sync(0xffffffffu, rs1, 1);
        rs1 += __shfl_xor_sync(0xffffffffu, rs1, 2);
        m0r = mn0; m1r = mn1;
        l0r = l0r*c0 + rs0;
        l1r = l1r*c1 + rs1;
#pragma unroll
        for (int nt = 0; nt < 16; nt++) {
            o[nt][0] *= c0; o[nt][1] *= c0;
            o[nt][2] *= c1; o[nt][3] *= c1;
        }

        // ---- P.V : O[16, 128] += P[16, 64] @ VT^T ----
#pragma unroll
        for (int kg = 0; kg < 4; kg++) {
            uint32_t aP[4];
            aP[0] = pack_f16(s[2*kg][0],   s[2*kg][1]);
            aP[1] = pack_f16(s[2*kg][2],   s[2*kg][3]);
            aP[2] = pack_f16(s[2*kg+1][0], s[2*kg+1][1]);
            aP[3] = pack_f16(s[2*kg+1][2], s[2*kg+1][3]);
#pragma unroll
            for (int np = 0; np < 8; np++) {
                uint32_t bH[4];
                uint32_t boff =
                    SW128((uint32_t)((np*16 + (lane&7) + (lane>>4)*8)*128
                                     + kg*32 + ((lane>>3)&1)*16));
                ldsm4(bH, vh + boff);
                mma16816(o[2*np],   aP, &bH[0]);
                mma16816(o[2*np+1], aP, &bH[2]);
            }
        }
        __syncthreads();
    }

    // ---- epilogue: O/l -> f16 into g_Ah ----
    float inv0 = 1.f / l0r, inv1 = 1.f / l1r;
    const size_t r0 = (size_t)(b*SEQ + q0 + warp*16 + g);
    const size_t r1 = r0 + 8;
#pragma unroll
    for (int nt = 0; nt < 16; nt++) {
        const int col = h*HD + nt*8 + tg*2;
        *(uint32_t*)&g_Ah[r0*HID + col] = pack_f16(o[nt][0]*inv0, o[nt][1]*inv0);
        *(uint32_t*)&g_Ah[r1*HID + col] = pack_f16(o[nt][2]*inv1, o[nt][3]*inv1);
    }
}

// ---------------- launch ----------------
extern "C" void kernel_launch(void* const* d_in, const int* in_sizes, int n_in,
                              void* d_out, int out_size)
{
    const float* X  = (const float*)d_in[0];
    const int* mask = (const int*)  d_in[1];
    const float* Wq = (const float*)d_in[2];
    const float* bq = (const float*)d_in[3];
    const float* Wk = (const float*)d_in[4];
    const float* bk = (const float*)d_in[5];
    const float* Wv = (const float*)d_in[6];
    const float* bv = (const float*)d_in[7];
    const float* Wo = (const float*)d_in[8];
    const float* bo = (const float*)d_in[9];
    float* out = (float*)d_out;

    float *vp, *bqkvp;
    cudaGetSymbolAddress((void**)&vp,    g_V);
    cudaGetSymbolAddress((void**)&bqkvp, g_bqkv);

    __half *xh, *qh, *ah, *kh, *wt, *wot;
    cudaGetSymbolAddress((void**)&xh,  g_Xh);
    cudaGetSymbolAddress((void**)&qh,  g_Qh);
    cudaGetSymbolAddress((void**)&ah,  g_Ah);
    cudaGetSymbolAddress((void**)&kh,  g_Kh);
    cudaGetSymbolAddress((void**)&wt,  g_WT);
    cudaGetSymbolAddress((void**)&wot, g_WoT);

    cudaFuncSetAttribute(gemm_mma_kernel<0>,
                         cudaFuncAttributeMaxDynamicSharedMemorySize, GEMM_DYN);
    cudaFuncSetAttribute(gemm_mma_kernel<1>,
                         cudaFuncAttributeMaxDynamicSharedMemorySize, GEMM_DYN);
    cudaFuncSetAttribute(attn_mma_kernel,
                         cudaFuncAttributeMaxDynamicSharedMemorySize, ATTN_DYN);

    const float scale = 0.088388347648318447f;  // 1/sqrt(128)

    // 1: all prep fused (xhalf, 4x weight transpose, bias concat, mask scan)
    prep_kernel<<<PREP_BLOCKS, 256>>>(X, mask, Wq, Wk, Wv, Wo, bq, bk, bv);

    // 2: fused QKV projection
    gemm_mma_kernel<1><<<dim3(NQKV/128, MTOT/128), 256, GEMM_DYN>>>(
        xh, wt, bqkvp, nullptr, qh, kh, vp, scale, MTOT, NQKV, HID);

    // 3: V transpose
    vtrans_kernel<<<dim3(SEQ/32, HD/32, BATCH), dim3(32,8)>>>();

    // 4: attention  (profiled slot)
    attn_mma_kernel<<<dim3(SEQ/128, NH, BATCH), 256, ATTN_DYN>>>(mask);

    // 5: output projection
    gemm_mma_kernel<0><<<dim3(HID/128, MTOT/128), 256, GEMM_DYN>>>(
        ah, wot, bo, out, nullptr, nullptr, nullptr, 1.f, MTOT, HID, HID);
}

// round 9
// speedup vs baseline: 15.7106x; 1.1081x over previous
#include <cuda_runtime.h>
#include <cuda_fp16.h>
#include <cstdint>
#include <math.h>

#define BATCH 2
#define SEQ   2048
#define HID   2048
#define NH    16
#define HD    128
#define MTOT  (BATCH*SEQ)
#define NQKV  2304   // 2048 (Q) + 128 (K) + 128 (V)

// ---------------- mma GEMM config (single f16, 3-stage pipeline) ----------------
#define CHUNK_BYTES 32768           // 2 tiles x 128rows x 128B (A, B)
#define GEMM_DYN    (3*CHUNK_BYTES + 1024)

// ---------------- mma attention config ----------------
#define BKV 64
#define ATTN_DYN (2*32768 + 1024)   // 2 KV bufs (Q staged in buf0 pre-loop)

// ---------------- device scratch ----------------
__device__ float  g_V[(size_t)MTOT*HD];     // V projection (fp32, pre-transpose)
__device__ int    g_anyzero = 0;            // sticky: any mask element == 0

__device__ __half g_Xh [(size_t)MTOT*HID];
__device__ __half g_Qh [(size_t)MTOT*HID];
__device__ __half g_Ah [(size_t)MTOT*HID];
__device__ __half g_Kh [(size_t)MTOT*HD];
__device__ __half g_VTh[(size_t)BATCH*HD*SEQ];
__device__ __half g_WT [(size_t)NQKV*HID];  // rows: WqT(0-2047) WkT(2048-2175) WvT(2176-2303)
__device__ __half g_WoT[(size_t)HID*HID];
__device__ float  g_bqkv[NQKV];

// ---------------- helpers ----------------
__device__ __forceinline__ uint32_t smem_u32(const void* p) {
    uint32_t a;
    asm("{ .reg .u64 t; cvta.to.shared.u64 t, %1; cvt.u32.u64 %0, t; }" : "=r"(a) : "l"(p));
    return a;
}
__device__ __forceinline__ void cp16(uint32_t dst, const void* src) {
    asm volatile("cp.async.cg.shared.global [%0], [%1], 16;" :: "r"(dst), "l"(src));
}
__device__ __forceinline__ void ldsm4(uint32_t* r, uint32_t addr) {
    asm volatile("ldmatrix.sync.aligned.m8n8.x4.shared.b16 {%0,%1,%2,%3}, [%4];"
                 : "=r"(r[0]), "=r"(r[1]), "=r"(r[2]), "=r"(r[3]) : "r"(addr));
}
__device__ __forceinline__ void mma16816(float* c, const uint32_t* a, const uint32_t* b) {
    asm volatile(
        "mma.sync.aligned.m16n8k16.row.col.f32.f16.f16.f32 "
        "{%0,%1,%2,%3}, {%4,%5,%6,%7}, {%8,%9}, {%0,%1,%2,%3};"
        : "+f"(c[0]), "+f"(c[1]), "+f"(c[2]), "+f"(c[3])
        : "r"(a[0]), "r"(a[1]), "r"(a[2]), "r"(a[3]), "r"(b[0]), "r"(b[1]));
}
// packed f16x2: lo in lower half, hi in upper half
__device__ __forceinline__ uint32_t pack_f16(float lo, float hi) {
    uint32_t r;
    asm("cvt.rn.f16x2.f32 %0, %1, %2;" : "=r"(r) : "f"(hi), "f"(lo));
    return r;
}
#define SW128(x) ((x) ^ (((x) >> 3) & 0x70))

// ---------------- fused prep kernel ----------------
#define PREP_BLOCKS 10249

__device__ __forceinline__ void ttrans_job(const float* __restrict__ W,
                                           __half* __restrict__ T,
                                           int K, int N, int bx, int by,
                                           float (*t)[33]) {
    int lx = threadIdx.x & 31;
    int ly = threadIdx.x >> 5;     // 0..7
    int x = bx*32 + lx;
#pragma unroll
    for (int j = 0; j < 4; j++) {
        int y = by*32 + ly + j*8;
        t[ly + j*8][lx] = W[(size_t)y*N + x];
    }
    __syncthreads();
    int xo = by*32 + lx;
#pragma unroll
    for (int j = 0; j < 4; j++) {
        int yo = bx*32 + ly + j*8;
        T[(size_t)yo*K + xo] = __float2half_rn(t[lx][ly + j*8]);
    }
}

__global__ __launch_bounds__(256) void prep_kernel(
    const float* __restrict__ X, const int* __restrict__ mask,
    const float* __restrict__ Wq, const float* __restrict__ Wk,
    const float* __restrict__ Wv, const float* __restrict__ Wo,
    const float* __restrict__ bq, const float* __restrict__ bk,
    const float* __restrict__ bv)
{
    __shared__ float t[32][33];
    const int bid = blockIdx.x;
    const int tid = threadIdx.x;

    if (bid < 1024) {                       // xhalf
        const int n4 = MTOT*HID/4;
        __half2* o2 = (__half2*)g_Xh;
        for (int i = bid*256 + tid; i < n4; i += 1024*256) {
            float4 v = ((const float4*)X)[i];
            o2[i*2+0] = __floats2half2_rn(v.x, v.y);
            o2[i*2+1] = __floats2half2_rn(v.z, v.w);
        }
    } else if (bid < 5120) {                // Wq transpose
        int i = bid - 1024;
        ttrans_job(Wq, g_WT, HID, HID, i & 63, i >> 6, t);
    } else if (bid < 5376) {                // Wk transpose
        int i = bid - 5120;
        ttrans_job(Wk, g_WT + (size_t)2048*HID, HID, HD, i & 3, i >> 2, t);
    } else if (bid < 5632) {                // Wv transpose
        int i = bid - 5376;
        ttrans_job(Wv, g_WT + (size_t)2176*HID, HID, HD, i & 3, i >> 2, t);
    } else if (bid < 5641) {                // bqkv concat
        int i = (bid - 5632)*256 + tid;
        if (i < NQKV)
            g_bqkv[i] = (i < 2048) ? bq[i] : (i < 2176 ? bk[i-2048] : bv[i-2176]);
    } else if (bid < 9737) {                // Wo transpose
        int i = bid - 5641;
        ttrans_job(Wo, g_WoT, HID, HID, i & 63, i >> 6, t);
    } else {                                // mask scan
        int base = bid - 9737;
        const int4* m4 = (const int4*)mask;
        const int total = BATCH*SEQ*SEQ/4;
        int bad = 0;
        for (int i = base*256 + tid; i < total; i += 512*256) {
            int4 v = m4[i];
            if ((v.x == 0) | (v.y == 0) | (v.z == 0) | (v.w == 0)) bad = 1;
        }
        if (bad) g_anyzero = 1;
    }
}

// ---------------- V fp32 -> VT[b][d][s] f16 transpose ----------------
__global__ void vtrans_kernel() {
    __shared__ float t[32][33];
    int b  = blockIdx.z;
    int s0 = blockIdx.x*32;
    int d0 = blockIdx.y*32;
#pragma unroll
    for (int j = 0; j < 4; j++) {
        int s = s0 + threadIdx.y + j*8;
        t[threadIdx.y + j*8][threadIdx.x] = g_V[((size_t)b*SEQ + s)*HD + d0 + threadIdx.x];
    }
    __syncthreads();
#pragma unroll
    for (int j = 0; j < 4; j++) {
        int d = d0 + threadIdx.y + j*8;
        g_VTh[((size_t)b*HD + d)*SEQ + s0 + threadIdx.x] =
            __float2half_rn(t[threadIdx.x][threadIdx.y + j*8]);
    }
}

// ---------------- mma.sync f16 GEMM (3-stage pipeline) ----------------
template<int EPI>
__global__ __launch_bounds__(256, 2) void gemm_mma_kernel(
    const __half* __restrict__ A, const __half* __restrict__ B,
    const float* __restrict__ bias, float* __restrict__ C,
    __half* __restrict__ Qf, __half* __restrict__ Kf, float* __restrict__ Vf,
    float oscale, int M, int N, int K)
{
    extern __shared__ char dyn[];
    const int tid  = threadIdx.x;
    const int warp = tid >> 5;
    const int lane = tid & 31;
    const int wm   = warp >> 2;
    const int wn   = warp & 3;
    const int n0 = blockIdx.x * 128;
    const int m0 = blockIdx.y * 128;

    const uint32_t sbase = (smem_u32(dyn) + 1023u) & ~1023u;

    float acc[4][4][4];
#pragma unroll
    for (int mt = 0; mt < 4; mt++)
#pragma unroll
        for (int nt = 0; nt < 4; nt++)
#pragma unroll
            for (int q = 0; q < 4; q++) acc[mt][nt][q] = 0.f;

    auto stage = [&](uint32_t tb, int k0) {
#pragma unroll
        for (int u = tid; u < 2048; u += 256) {
            int t   = u >> 10;
            int idx = u & 1023;
            int row = idx >> 3;
            int c16 = idx & 7;
            const __half* src = t ? (B + (size_t)(n0+row)*K + k0 + c16*8)
                                  : (A + (size_t)(m0+row)*K + k0 + c16*8);
            cp16(tb + t*16384 + SW128((uint32_t)(row*128 + c16*16)), src);
        }
        asm volatile("cp.async.commit_group;" ::: "memory");
    };

    const int nch = K / 64;
    stage(sbase, 0);
    if (nch > 1) stage(sbase + CHUNK_BYTES, 64);

    for (int ch = 0; ch < nch; ch++) {
        if (ch + 2 < nch) {
            stage(sbase + ((ch+2)%3)*CHUNK_BYTES, (ch+2)*64);
            asm volatile("cp.async.wait_group 2;" ::: "memory");
        } else if (ch + 1 < nch) {
            asm volatile("cp.async.wait_group 1;" ::: "memory");
        } else {
            asm volatile("cp.async.wait_group 0;" ::: "memory");
        }
        __syncthreads();

        const uint32_t tb = sbase + (ch%3)*CHUNK_BYTES;
        const uint32_t tA = tb, tB = tb + 16384;

#pragma unroll
        for (int ks = 0; ks < 4; ks++) {
            uint32_t ah[4][4], bh[2][4];
            const uint32_t abyte = (uint32_t)(ks*32 + (lane>>4)*16);
            const int      arow  = wm*64 + (lane & 15);
#pragma unroll
            for (int mt = 0; mt < 4; mt++)
                ldsm4(ah[mt], tA + SW128((uint32_t)((arow + mt*16)*128) + abyte));
            const uint32_t bbyte = (uint32_t)(ks*32 + ((lane>>3)&1)*16);
            const int      brow  = wn*32 + (lane & 7) + (lane>>4)*8;
#pragma unroll
            for (int np = 0; np < 2; np++)
                ldsm4(bh[np], tB + SW128((uint32_t)((brow + np*16)*128) + bbyte));
#pragma unroll
            for (int mt = 0; mt < 4; mt++)
#pragma unroll
                for (int nt = 0; nt < 4; nt++)
                    mma16816(acc[mt][nt], ah[mt], &bh[nt>>1][(nt&1)*2]);
        }
        __syncthreads();
    }

    const int g  = lane >> 2;
    const int tg = lane & 3;
#pragma unroll
    for (int mt = 0; mt < 4; mt++) {
        const int r0 = m0 + wm*64 + mt*16 + g;
#pragma unroll
        for (int nt = 0; nt < 4; nt++) {
            const int col = n0 + wn*32 + nt*8 + tg*2;
            const float b0 = bias[col], b1 = bias[col+1];
            float v0 = acc[mt][nt][0] + b0, v1 = acc[mt][nt][1] + b1;
            float v2 = acc[mt][nt][2] + b0, v3 = acc[mt][nt][3] + b1;
            if (EPI == 0) {
                *(float2*)&C[(size_t)r0*N + col]     = make_float2(v0, v1);
                *(float2*)&C[(size_t)(r0+8)*N + col] = make_float2(v2, v3);
            } else {
                if (n0 < 2048) {           // Q: f16 scaled
                    *(uint32_t*)&Qf[(size_t)r0*HID + col] =
                        pack_f16(v0*oscale, v1*oscale);
                    *(uint32_t*)&Qf[(size_t)(r0+8)*HID + col] =
                        pack_f16(v2*oscale, v3*oscale);
                } else if (n0 < 2176) {    // K: f16
                    const int d = col - 2048;
                    *(uint32_t*)&Kf[(size_t)r0*HD + d]     = pack_f16(v0, v1);
                    *(uint32_t*)&Kf[(size_t)(r0+8)*HD + d] = pack_f16(v2, v3);
                } else {                   // V: fp32 (pre-transpose)
                    const int d = col - 2176;
                    *(float2*)&Vf[(size_t)r0*HD + d]     = make_float2(v0, v1);
                    *(float2*)&Vf[(size_t)(r0+8)*HD + d] = make_float2(v2, v3);
                }
            }
        }
    }
}

// ---------------- mma.sync flash attention (f16, Q in registers) ----------------
// grid (SEQ/64, NH, BATCH), 128 threads (4 warps x 16 q-rows = 64 q-rows/CTA).
// 2 CTAs/SM: regs ~190 x 128 x 2 < 64K; smem 65KB x 2 < 228KB.
__global__ __launch_bounds__(128, 2) void attn_mma_kernel(const int* __restrict__ mask)
{
    extern __shared__ char dyn[];
    const int tid  = threadIdx.x;
    const int warp = tid >> 5;
    const int lane = tid & 31;
    const int g    = lane >> 2;
    const int tg   = lane & 3;
    const int h  = blockIdx.y;
    const int b  = blockIdx.z;
    const int q0 = blockIdx.x * 64;
    const int allones = (g_anyzero == 0);

    const uint32_t base = (smem_u32(dyn) + 1023u) & ~1023u;
    // per-buf (32KB): K tile @0 (16KB, 2 chunks of 8KB), VT tile @16384 (16KB)

    // ---- stage Q into buf0 (64 rows x 128d, 2 chunks of 64d) ----
    for (int u = tid; u < 1024; u += 128) {
        int chunk = u >> 9, r = (u >> 3) & 63, c16 = u & 7;
        const __half* src =
            g_Qh + ((size_t)(b*SEQ + q0 + r))*HID + h*HD + chunk*64 + c16*8;
        cp16(base + chunk*8192 + SW128((uint32_t)(r*128 + c16*16)), src);
    }
    asm volatile("cp.async.commit_group;" ::: "memory");
    asm volatile("cp.async.wait_group 0;" ::: "memory");
    __syncthreads();

    // ---- Q fragments -> registers (freed smem reused for KV pipeline) ----
    uint32_t qf[8][4];
#pragma unroll
    for (int ks = 0; ks < 8; ks++) {
        uint32_t aoff = (ks>>2)*8192 +
            SW128((uint32_t)((warp*16 + (lane & 15))*128 + (ks&3)*32 + (lane>>4)*16));
        ldsm4(qf[ks], base + aoff);
    }
    __syncthreads();   // all warps done reading Q before buf0 is overwritten

    auto stageKV = [&](uint32_t bb, int j0) {
#pragma unroll
        for (int u = tid; u < 1024; u += 128) {   // K tile [64 tok][128 d]
            int chunk = u >> 9, r = (u >> 3) & 63, c16 = u & 7;
            const __half* src =
                g_Kh + ((size_t)(b*SEQ + j0 + r))*HD + chunk*64 + c16*8;
            cp16(bb + chunk*8192 + SW128((uint32_t)(r*128 + c16*16)), src);
        }
#pragma unroll
        for (int u = tid; u < 1024; u += 128) {   // VT tile [128 d][64 tok]
            int r = u >> 3, c16 = u & 7;
            const __half* src = g_VTh + ((size_t)b*HD + r)*SEQ + j0 + c16*8;
            cp16(bb + 16384 + SW128((uint32_t)(r*128 + c16*16)), src);
        }
        asm volatile("cp.async.commit_group;" ::: "memory");
    };

    const int NT = SEQ / BKV;
    stageKV(base, 0);
    stageKV(base + 32768, BKV);

    float m0r = -1e30f, m1r = -1e30f, l0r = 0.f, l1r = 0.f;
    float o[16][4];
#pragma unroll
    for (int nt = 0; nt < 16; nt++)
#pragma unroll
        for (int e = 0; e < 4; e++) o[nt][e] = 0.f;

    for (int t = 0; t < NT; t++) {
        if (t + 1 < NT) {
            asm volatile("cp.async.wait_group 1;" ::: "memory");
        } else {
            asm volatile("cp.async.wait_group 0;" ::: "memory");
        }
        __syncthreads();

        const uint32_t bb = base + (t&1)*32768;
        const uint32_t kh = bb, vh = bb + 16384;
        const int j0 = t * BKV;

        // ---- scores S[16, 64] = Q @ K^T ----
        float s[8][4];
#pragma unroll
        for (int nt = 0; nt < 8; nt++)
#pragma unroll
            for (int e = 0; e < 4; e++) s[nt][e] = 0.f;

#pragma unroll
        for (int ks = 0; ks < 8; ks++) {
#pragma unroll
            for (int np = 0; np < 4; np++) {
                uint32_t bH[4];
                uint32_t boff = (ks>>2)*8192 +
                    SW128((uint32_t)((np*16 + (lane&7) + (lane>>4)*8)*128
                                     + (ks&3)*32 + ((lane>>3)&1)*16));
                ldsm4(bH, kh + boff);
                mma16816(s[2*np],   qf[ks], &bH[0]);
                mma16816(s[2*np+1], qf[ks], &bH[2]);
            }
        }

        if (!allones) {
#pragma unroll
            for (int nt = 0; nt < 8; nt++)
#pragma unroll
                for (int e = 0; e < 4; e++) {
                    int qr = q0 + warp*16 + g + ((e>>1)<<3);
                    int kc = j0 + nt*8 + tg*2 + (e&1);
                    if (mask[((size_t)b*SEQ + qr)*SEQ + kc] == 0) s[nt][e] = -1e30f;
                }
        }

        // ---- online softmax (rows g, g+8; quad lanes share a row) ----
        float rm0 = s[0][0], rm1 = s[0][2];
#pragma unroll
        for (int nt = 0; nt < 8; nt++) {
            rm0 = fmaxf(rm0, fmaxf(s[nt][0], s[nt][1]));
            rm1 = fmaxf(rm1, fmaxf(s[nt][2], s[nt][3]));
        }
        rm0 = fmaxf(rm0, __shfl_xor_sync(0xffffffffu, rm0, 1));
        rm0 = fmaxf(rm0, __shfl_xor_sync(0xffffffffu, rm0, 2));
        rm1 = fmaxf(rm1, __shfl_xor_sync(0xffffffffu, rm1, 1));
        rm1 = fmaxf(rm1, __shfl_xor_sync(0xffffffffu, rm1, 2));
        float mn0 = fmaxf(m0r, rm0), mn1 = fmaxf(m1r, rm1);
        float c0 = __expf(m0r - mn0), c1 = __expf(m1r - mn1);
        float rs0 = 0.f, rs1 = 0.f;
#pragma unroll
        for (int nt = 0; nt < 8; nt++) {
            s[nt][0] = __expf(s[nt][0] - mn0);
            s[nt][1] = __expf(s[nt][1] - mn0);
            s[nt][2] = __expf(s[nt][2] - mn1);
            s[nt][3] = __expf(s[nt][3] - mn1);
            rs0 += s[nt][0] + s[nt][1];
            rs1 += s[nt][2] + s[nt][3];
        }
        rs0 += __shfl_xor_sync(0xffffffffu, rs0, 1);
        rs0 += __shfl_xor_sync(0xffffffffu, rs0, 2);
        rs1 += __shfl_xor_sync(0xffffffffu, rs1, 1);
        rs1 += __shfl_xor_sync(0xffffffffu, rs1, 2);

        // warp-vote rescale skip: only rescale O when some row max advanced
        if (__any_sync(0xffffffffu, (mn0 > m0r) | (mn1 > m1r))) {
#pragma unroll
            for (int nt = 0; nt < 16; nt++) {
                o[nt][0] *= c0; o[nt][1] *= c0;
                o[nt][2] *= c1; o[nt][3] *= c1;
            }
        }
        m0r = mn0; m1r = mn1;
        l0r = l0r*c0 + rs0;
        l1r = l1r*c1 + rs1;

        // ---- P.V : O[16, 128] += P[16, 64] @ VT^T ----
#pragma unroll
        for (int kg = 0; kg < 4; kg++) {
            uint32_t aP[4];
            aP[0] = pack_f16(s[2*kg][0],   s[2*kg][1]);
            aP[1] = pack_f16(s[2*kg][2],   s[2*kg][3]);
            aP[2] = pack_f16(s[2*kg+1][0], s[2*kg+1][1]);
            aP[3] = pack_f16(s[2*kg+1][2], s[2*kg+1][3]);
#pragma unroll
            for (int np = 0; np < 8; np++) {
                uint32_t bH[4];
                uint32_t boff =
                    SW128((uint32_t)((np*16 + (lane&7) + (lane>>4)*8)*128
                                     + kg*32 + ((lane>>3)&1)*16));
                ldsm4(bH, vh + boff);
                mma16816(o[2*np],   aP, &bH[0]);
                mma16816(o[2*np+1], aP, &bH[2]);
            }
        }
        __syncthreads();   // all warps done with buf (t&1) before restage

        if (t + 2 < NT) stageKV(base + (t&1)*32768, (t+2)*BKV);
    }

    // ---- epilogue: O/l -> f16 into g_Ah ----
    float inv0 = 1.f / l0r, inv1 = 1.f / l1r;
    const size_t r0 = (size_t)(b*SEQ + q0 + warp*16 + g);
    const size_t r1 = r0 + 8;
#pragma unroll
    for (int nt = 0; nt < 16; nt++) {
        const int col = h*HD + nt*8 + tg*2;
        *(uint32_t*)&g_Ah[r0*HID + col] = pack_f16(o[nt][0]*inv0, o[nt][1]*inv0);
        *(uint32_t*)&g_Ah[r1*HID + col] = pack_f16(o[nt][2]*inv1, o[nt][3]*inv1);
    }
}

// ---------------- launch ----------------
extern "C" void kernel_launch(void* const* d_in, const int* in_sizes, int n_in,
                              void* d_out, int out_size)
{
    const float* X  = (const float*)d_in[0];
    const int* mask = (const int*)  d_in[1];
    const float* Wq = (const float*)d_in[2];
    const float* bq = (const float*)d_in[3];
    const float* Wk = (const float*)d_in[4];
    const float* bk = (const float*)d_in[5];
    const float* Wv = (const float*)d_in[6];
    const float* bv = (const float*)d_in[7];
    const float* Wo = (const float*)d_in[8];
    const float* bo = (const float*)d_in[9];
    float* out = (float*)d_out;

    float *vp, *bqkvp;
    cudaGetSymbolAddress((void**)&vp,    g_V);
    cudaGetSymbolAddress((void**)&bqkvp, g_bqkv);

    __half *xh, *qh, *ah, *kh, *wt, *wot;
    cudaGetSymbolAddress((void**)&xh,  g_Xh);
    cudaGetSymbolAddress((void**)&qh,  g_Qh);
    cudaGetSymbolAddress((void**)&ah,  g_Ah);
    cudaGetSymbolAddress((void**)&kh,  g_Kh);
    cudaGetSymbolAddress((void**)&wt,  g_WT);
    cudaGetSymbolAddress((void**)&wot, g_WoT);

    cudaFuncSetAttribute(gemm_mma_kernel<0>,
                         cudaFuncAttributeMaxDynamicSharedMemorySize, GEMM_DYN);
    cudaFuncSetAttribute(gemm_mma_kernel<1>,
                         cudaFuncAttributeMaxDynamicSharedMemorySize, GEMM_DYN);
    cudaFuncSetAttribute(attn_mma_kernel,
                         cudaFuncAttributeMaxDynamicSharedMemorySize, ATTN_DYN);

    const float scale = 0.088388347648318447f;  // 1/sqrt(128)

    // 1: all prep fused (xhalf, 4x weight transpose, bias concat, mask scan)
    prep_kernel<<<PREP_BLOCKS, 256>>>(X, mask, Wq, Wk, Wv, Wo, bq, bk, bv);

    // 2: fused QKV projection
    gemm_mma_kernel<1><<<dim3(NQKV/128, MTOT/128), 256, GEMM_DYN>>>(
        xh, wt, bqkvp, nullptr, qh, kh, vp, scale, MTOT, NQKV, HID);

    // 3: V transpose
    vtrans_kernel<<<dim3(SEQ/32, HD/32, BATCH), dim3(32,8)>>>();

    // 4: attention  (profiled slot)
    attn_mma_kernel<<<dim3(SEQ/64, NH, BATCH), 128, ATTN_DYN>>>(mask);

    // 5: output projection
    gemm_mma_kernel<0><<<dim3(HID/128, MTOT/128), 256, GEMM_DYN>>>(
        ah, wot, bo, out, nullptr, nullptr, nullptr, 1.f, MTOT, HID, HID);
}